// round 1
// baseline (speedup 1.0000x reference)
#include <cuda_runtime.h>
#include <math.h>

#define B_ 2
#define T_ 2048
#define C_ 2048
#define H_ 16
#define HKV_ 4
#define D_ 128
#define WINDOW_ 1024
#define SINK_ 4
#define KVC_ (HKV_ * D_)   // 512
#define SCALE_ 0.08838834764831845f  // 1/sqrt(128)

// Scratch (static device globals; no runtime allocation)
__device__ float g_q[B_ * T_ * C_];     // [B*T, 2048]
__device__ float g_k[B_ * T_ * KVC_];   // [B*T, 512]
__device__ float g_v[B_ * T_ * KVC_];   // [B*T, 512]
__device__ float g_y[B_ * T_ * C_];     // attention output, pre-Wo

// ---------------------------------------------------------------------------
// SGEMM: C[M,N] = A[M,K] @ B[K,N], all row-major, fp32.
// 128x128 tile, BK=8, 256 threads, 8x8 per thread, float4 everywhere.
// Requires M%128==0, N%128==0, K%8==0 (true for all our shapes).
// ---------------------------------------------------------------------------
#define GBM 128
#define GBN 128
#define GBK 8

__global__ __launch_bounds__(256, 2)
void sgemm_kernel(const float* __restrict__ A, const float* __restrict__ B,
                  float* __restrict__ C, int M, int N, int K) {
    __shared__ float As[GBK][GBM];
    __shared__ float Bs[GBK][GBN];

    const int tid = threadIdx.x;
    const int brow = blockIdx.y * GBM;
    const int bcol = blockIdx.x * GBN;

    // A tile load mapping: 128 rows x 8 k-cols, one float4 per thread
    const int arow = tid >> 1;
    const int acol = (tid & 1) * 4;
    // B tile load mapping: 8 k-rows x 128 cols, one float4 per thread
    const int brb = tid >> 5;
    const int bcb = (tid & 31) * 4;

    const int tx = tid & 15;
    const int ty = tid >> 4;

    float acc[8][8];
#pragma unroll
    for (int i = 0; i < 8; i++)
#pragma unroll
        for (int j = 0; j < 8; j++) acc[i][j] = 0.0f;

    const float* Aptr = A + (long)(brow + arow) * K + acol;
    const float* Bptr = B + (long)brb * N + bcol + bcb;

    for (int k0 = 0; k0 < K; k0 += GBK) {
        float4 a4 = *(const float4*)(Aptr + k0);
        As[acol + 0][arow] = a4.x;
        As[acol + 1][arow] = a4.y;
        As[acol + 2][arow] = a4.z;
        As[acol + 3][arow] = a4.w;
        float4 b4 = *(const float4*)(Bptr + (long)k0 * N);
        *(float4*)&Bs[brb][bcb] = b4;
        __syncthreads();

#pragma unroll
        for (int kk = 0; kk < GBK; kk++) {
            float a[8], b[8];
            *(float4*)(a)     = *(const float4*)&As[kk][ty * 8];
            *(float4*)(a + 4) = *(const float4*)&As[kk][ty * 8 + 4];
            *(float4*)(b)     = *(const float4*)&Bs[kk][tx * 8];
            *(float4*)(b + 4) = *(const float4*)&Bs[kk][tx * 8 + 4];
#pragma unroll
            for (int i = 0; i < 8; i++)
#pragma unroll
                for (int j = 0; j < 8; j++) acc[i][j] += a[i] * b[j];
        }
        __syncthreads();
    }

#pragma unroll
    for (int i = 0; i < 8; i++) {
        float* Crow = C + (long)(brow + ty * 8 + i) * N + bcol + tx * 8;
        *(float4*)(Crow)     = make_float4(acc[i][0], acc[i][1], acc[i][2], acc[i][3]);
        *(float4*)(Crow + 4) = make_float4(acc[i][4], acc[i][5], acc[i][6], acc[i][7]);
    }
}

// ---------------------------------------------------------------------------
// RoPE (in place). buf is [B*T, heads*128]. One thread per (bt, h, i<64) pair.
// out[i]    = x[i]*cos(t*f_i)    - x[i+64]*sin(t*f_i)
// out[i+64] = x[i+64]*cos(t*f_i) + x[i]*sin(t*f_i)
// f_i = 10000^(-2i/128)
// ---------------------------------------------------------------------------
__global__ void rope_kernel(float* __restrict__ buf, int heads, int total) {
    int idx = blockIdx.x * blockDim.x + threadIdx.x;
    if (idx >= total) return;
    int i = idx & 63;
    int h = (idx >> 6) % heads;
    int bt = idx / (64 * heads);
    int t = bt & (T_ - 1);

    float inv = powf(10000.0f, -(float)(2 * i) / 128.0f);
    float ang = (float)t * inv;
    float s, c;
    sincosf(ang, &s, &c);

    float* p = buf + ((long)bt * heads + h) * 128;
    float x1 = p[i];
    float x2 = p[i + 64];
    p[i]      = x1 * c - x2 * s;
    p[i + 64] = x2 * c + x1 * s;
}

// ---------------------------------------------------------------------------
// Flash attention (fp32). Block = 256 threads = 8 warps; BQ=32 queries/block
// (4 per warp), key tiles of 32. lane = key within tile.
// Grid: (T/32, H, B).
// Masking: k<=q && (q-k<=WINDOW || k<SINK). Rows with q>=seq_len write 0.
// ---------------------------------------------------------------------------
#define BQ 32
#define TK 32
#define KS_STRIDE 129   // conflict-free for Ks[lane][d] reads

__global__ __launch_bounds__(256)
void attn_kernel(const int* __restrict__ seq_lengths) {
    extern __shared__ float smem[];
    float* Qs = smem;                       // [32][128]
    float* Ks = Qs + BQ * 128;              // [32][129]
    float* Vs = Ks + TK * KS_STRIDE;        // [32][128]

    const int b = blockIdx.z;
    const int h = blockIdx.y;
    const int q0 = blockIdx.x * BQ;
    const int hk = h >> 2;
    const int tid = threadIdx.x;
    const int warp = tid >> 5;
    const int lane = tid & 31;
    const int seqlen = seq_lengths[b];

    // Load Q tile: row = tid/8, 16 consecutive dims per thread
    {
        int r = tid >> 3;
        int c0 = (tid & 7) * 16;
        const float* src = g_q + ((long)(b * T_ + q0 + r)) * C_ + h * 128 + c0;
        float* dst = Qs + r * 128 + c0;
#pragma unroll
        for (int j = 0; j < 16; j += 4) *(float4*)(dst + j) = *(const float4*)(src + j);
    }

    float m[4], l[4], o[4][4];
#pragma unroll
    for (int j = 0; j < 4; j++) {
        m[j] = -1e30f;
        l[j] = 0.0f;
#pragma unroll
        for (int d = 0; d < 4; d++) o[j][d] = 0.0f;
    }

    const int kthi = q0 / TK;
    int ktlo = (q0 > WINDOW_) ? (q0 - WINDOW_) / TK : 0;
    const int extra = (ktlo > 0) ? 1 : 0;   // separate sink tile (kt=0)
    const int nt = (kthi - ktlo + 1) + extra;

    for (int it = 0; it < nt; it++) {
        const int kt = extra ? ((it == 0) ? 0 : (ktlo + it - 1)) : it;
        const int kbase = kt * TK;

        __syncthreads();  // previous tile's smem reads done
        // Load K (padded stride, scalar stores) and V (stride 128, float4)
        {
            int r = tid >> 3;
            int c0 = (tid & 7) * 16;
            const float* ksrc = g_k + ((long)(b * T_ + kbase + r)) * KVC_ + hk * 128 + c0;
            const float* vsrc = g_v + ((long)(b * T_ + kbase + r)) * KVC_ + hk * 128 + c0;
            float* kd = Ks + r * KS_STRIDE + c0;
            float* vd = Vs + r * 128 + c0;
#pragma unroll
            for (int j = 0; j < 16; j++) kd[j] = ksrc[j];
#pragma unroll
            for (int j = 0; j < 16; j += 4) *(float4*)(vd + j) = *(const float4*)(vsrc + j);
        }
        __syncthreads();

        // Scores: this lane's key vs this warp's 4 queries
        float s[4] = {0.0f, 0.0f, 0.0f, 0.0f};
        {
            const float* krow = Ks + lane * KS_STRIDE;
            const float* qp = Qs + (warp * 4) * 128;
#pragma unroll 4
            for (int d = 0; d < 128; d++) {
                float kd = krow[d];
                s[0] += qp[d] * kd;
                s[1] += qp[128 + d] * kd;
                s[2] += qp[256 + d] * kd;
                s[3] += qp[384 + d] * kd;
            }
        }

        // Mask + online softmax update
        float pv[4];
#pragma unroll
        for (int j = 0; j < 4; j++) {
            int q = q0 + warp * 4 + j;
            int k = kbase + lane;
            bool ok = (k <= q) && (((q - k) <= WINDOW_) || (k < SINK_));
            float sv = ok ? s[j] * SCALE_ : -1e30f;

            float mx = sv;
#pragma unroll
            for (int off = 16; off > 0; off >>= 1)
                mx = fmaxf(mx, __shfl_xor_sync(0xffffffffu, mx, off));
            float mnew = fmaxf(m[j], mx);
            float p = __expf(sv - mnew);
            float alpha = __expf(m[j] - mnew);

            float ps = p;
#pragma unroll
            for (int off = 16; off > 0; off >>= 1)
                ps += __shfl_xor_sync(0xffffffffu, ps, off);

            l[j] = l[j] * alpha + ps;
            m[j] = mnew;
#pragma unroll
            for (int d = 0; d < 4; d++) o[j][d] *= alpha;
            pv[j] = p;
        }

        // PV: lane owns dims lane*4..+3; broadcast p over keys via shfl
#pragma unroll 4
        for (int k = 0; k < TK; k++) {
            float4 vv = *(const float4*)(Vs + k * 128 + lane * 4);
            float p0 = __shfl_sync(0xffffffffu, pv[0], k);
            float p1 = __shfl_sync(0xffffffffu, pv[1], k);
            float p2 = __shfl_sync(0xffffffffu, pv[2], k);
            float p3 = __shfl_sync(0xffffffffu, pv[3], k);
            o[0][0] += p0 * vv.x; o[0][1] += p0 * vv.y; o[0][2] += p0 * vv.z; o[0][3] += p0 * vv.w;
            o[1][0] += p1 * vv.x; o[1][1] += p1 * vv.y; o[1][2] += p1 * vv.z; o[1][3] += p1 * vv.w;
            o[2][0] += p2 * vv.x; o[2][1] += p2 * vv.y; o[2][2] += p2 * vv.z; o[2][3] += p2 * vv.w;
            o[3][0] += p3 * vv.x; o[3][1] += p3 * vv.y; o[3][2] += p3 * vv.z; o[3][3] += p3 * vv.w;
        }
    }

    // Epilogue: normalize, zero invalid rows
#pragma unroll
    for (int j = 0; j < 4; j++) {
        int q = q0 + warp * 4 + j;
        float invl = (q < seqlen) ? (1.0f / l[j]) : 0.0f;
        float* dst = g_y + ((long)(b * T_ + q)) * C_ + h * 128 + lane * 4;
        *(float4*)dst = make_float4(o[j][0] * invl, o[j][1] * invl,
                                    o[j][2] * invl, o[j][3] * invl);
    }
}

// ---------------------------------------------------------------------------
// Launch
// ---------------------------------------------------------------------------
extern "C" void kernel_launch(void* const* d_in, const int* in_sizes, int n_in,
                              void* d_out, int out_size) {
    const float* x  = (const float*)d_in[0];
    const float* Wq = (const float*)d_in[1];
    const float* Wk = (const float*)d_in[2];
    const float* Wv = (const float*)d_in[3];
    const float* Wo = (const float*)d_in[4];
    const int* seq_lengths = (const int*)d_in[5];
    float* out = (float*)d_out;

    float* q_ptr; cudaGetSymbolAddress((void**)&q_ptr, g_q);
    float* k_ptr; cudaGetSymbolAddress((void**)&k_ptr, g_k);
    float* v_ptr; cudaGetSymbolAddress((void**)&v_ptr, g_v);
    float* y_ptr; cudaGetSymbolAddress((void**)&y_ptr, g_y);

    const int M = B_ * T_;  // 4096

    // QKV projections
    sgemm_kernel<<<dim3(C_ / GBN, M / GBM), 256>>>(x, Wq, q_ptr, M, C_, C_);
    sgemm_kernel<<<dim3(KVC_ / GBN, M / GBM), 256>>>(x, Wk, k_ptr, M, KVC_, C_);
    sgemm_kernel<<<dim3(KVC_ / GBN, M / GBM), 256>>>(x, Wv, v_ptr, M, KVC_, C_);

    // RoPE on q and k
    {
        int total_q = M * H_ * 64;
        int total_k = M * HKV_ * 64;
        rope_kernel<<<(total_q + 255) / 256, 256>>>(q_ptr, H_, total_q);
        rope_kernel<<<(total_k + 255) / 256, 256>>>(k_ptr, HKV_, total_k);
    }

    // Attention
    {
        size_t smem_bytes = (size_t)(BQ * 128 + TK * KS_STRIDE + TK * 128) * sizeof(float);
        cudaFuncSetAttribute((const void*)attn_kernel,
                             cudaFuncAttributeMaxDynamicSharedMemorySize,
                             (int)smem_bytes);
        attn_kernel<<<dim3(T_ / BQ, H_, B_), 256, smem_bytes>>>(seq_lengths);
    }

    // Output projection
    sgemm_kernel<<<dim3(C_ / GBN, M / GBM), 256>>>(y_ptr, Wo, out, M, C_, C_);
}

// round 4
// speedup vs baseline: 1.7249x; 1.7249x over previous
#include <cuda_runtime.h>
#include <cuda_bf16.h>
#include <cstdint>
#include <math.h>

#define B_ 2
#define T_ 2048
#define C_ 2048
#define H_ 16
#define HKV_ 4
#define D_ 128
#define WINDOW_ 1024
#define SINK_ 4
#define KVC_ (HKV_ * D_)   // 512
#define SCALE_ 0.08838834764831845f  // 1/sqrt(128)

extern __shared__ char dynsmem[];

__device__ __forceinline__ uint32_t smem_to_u32(const void* p) {
    uint32_t a;
    asm("{ .reg .u64 t; cvta.to.shared.u64 t, %1; cvt.u32.u64 %0, t; }" : "=r"(a) : "l"(p));
    return a;
}

// ---------------------------------------------------------------------------
// Scratch buffers
// ---------------------------------------------------------------------------
__device__ float g_q[B_ * T_ * C_];
__device__ float g_k[B_ * T_ * KVC_];
__device__ float g_v[B_ * T_ * KVC_];
__device__ float g_y[B_ * T_ * C_];

__device__ __nv_bfloat16 g_xhi[B_ * T_ * C_], g_xlo[B_ * T_ * C_];
__device__ __nv_bfloat16 g_yhi[B_ * T_ * C_], g_ylo[B_ * T_ * C_];
__device__ __nv_bfloat16 g_wqh[C_ * C_],   g_wql[C_ * C_];     // [N][K] transposed
__device__ __nv_bfloat16 g_wkh[KVC_ * C_], g_wkl[KVC_ * C_];
__device__ __nv_bfloat16 g_wvh[KVC_ * C_], g_wvl[KVC_ * C_];
__device__ __nv_bfloat16 g_woh[C_ * C_],   g_wol[C_ * C_];

// ---------------------------------------------------------------------------
// Split: f32 -> (hi, lo) bf16
// ---------------------------------------------------------------------------
__global__ void split_kernel(const float* __restrict__ in,
                             __nv_bfloat16* __restrict__ hi,
                             __nv_bfloat16* __restrict__ lo, int n) {
    int i = (blockIdx.x * blockDim.x + threadIdx.x) * 4;
    if (i >= n) return;
    float4 v = *(const float4*)(in + i);
    __nv_bfloat16 h0 = __float2bfloat16(v.x);
    __nv_bfloat16 h1 = __float2bfloat16(v.y);
    __nv_bfloat16 h2 = __float2bfloat16(v.z);
    __nv_bfloat16 h3 = __float2bfloat16(v.w);
    __nv_bfloat16 l0 = __float2bfloat16(v.x - __bfloat162float(h0));
    __nv_bfloat16 l1 = __float2bfloat16(v.y - __bfloat162float(h1));
    __nv_bfloat16 l2 = __float2bfloat16(v.z - __bfloat162float(h2));
    __nv_bfloat16 l3 = __float2bfloat16(v.w - __bfloat162float(h3));
    *(__nv_bfloat162*)(hi + i)     = __nv_bfloat162(h0, h1);
    *(__nv_bfloat162*)(hi + i + 2) = __nv_bfloat162(h2, h3);
    *(__nv_bfloat162*)(lo + i)     = __nv_bfloat162(l0, l1);
    *(__nv_bfloat162*)(lo + i + 2) = __nv_bfloat162(l2, l3);
}

// ---------------------------------------------------------------------------
// Transpose + split: W [K,N] f32 -> Wt_hi/Wt_lo [N,K] bf16
// ---------------------------------------------------------------------------
__global__ void tsplit_kernel(const float* __restrict__ W,
                              __nv_bfloat16* __restrict__ thi,
                              __nv_bfloat16* __restrict__ tlo, int K, int N) {
    __shared__ float tile[32][33];
    int kb = blockIdx.y * 32, nb = blockIdx.x * 32;
    int tx = threadIdx.x, ty = threadIdx.y;
#pragma unroll
    for (int r = 0; r < 4; r++)
        tile[ty + r * 8][tx] = W[(size_t)(kb + ty + r * 8) * N + nb + tx];
    __syncthreads();
#pragma unroll
    for (int r = 0; r < 4; r++) {
        int n = nb + ty + r * 8;
        int k = kb + tx;
        float v = tile[tx][ty + r * 8];
        __nv_bfloat16 h = __float2bfloat16(v);
        thi[(size_t)n * K + k] = h;
        tlo[(size_t)n * K + k] = __float2bfloat16(v - __bfloat162float(h));
    }
}

// ---------------------------------------------------------------------------
// mma.sync bf16 split GEMM: C[M,N] = A[M,K] @ Bt[N,K]^T, fp32-class accuracy.
// CTA 128x128, BK=32, 8 warps (2x4), warp tile 64x32, m16n8k16 HMMA.
// Passes per k-step: Ahi*Bhi + Ahi*Blo + Alo*Bhi (ll dropped, ~1.5e-5 rel).
// Smem rows padded to 80B (stride 20 words) -> conflict-free ldmatrix.
// ---------------------------------------------------------------------------
#define ROWB 80                       // bytes per smem row (64 data + 16 pad)
#define OPTILE (128 * ROWB)           // 10240 B per operand tile
#define STAGEB (4 * OPTILE)           // 40960 B per stage
#define GSMEM_TOTAL (2 * STAGEB)      // 81920 B

__device__ __forceinline__ void ldsm_x4(uint32_t* r, uint32_t addr) {
    asm volatile("ldmatrix.sync.aligned.m8n8.x4.shared.b16 {%0,%1,%2,%3}, [%4];"
                 : "=r"(r[0]), "=r"(r[1]), "=r"(r[2]), "=r"(r[3]) : "r"(addr));
}
__device__ __forceinline__ void mma16816(float* d, const uint32_t* a, const uint32_t* b) {
    asm volatile(
        "mma.sync.aligned.m16n8k16.row.col.f32.bf16.bf16.f32 "
        "{%0,%1,%2,%3}, {%4,%5,%6,%7}, {%8,%9}, {%0,%1,%2,%3};"
        : "+f"(d[0]), "+f"(d[1]), "+f"(d[2]), "+f"(d[3])
        : "r"(a[0]), "r"(a[1]), "r"(a[2]), "r"(a[3]), "r"(b[0]), "r"(b[1]));
}

__global__ __launch_bounds__(256, 1)
void gemm_bf16split_kernel(const __nv_bfloat16* __restrict__ Ahi,
                           const __nv_bfloat16* __restrict__ Alo,
                           const __nv_bfloat16* __restrict__ Bhi,
                           const __nv_bfloat16* __restrict__ Blo,
                           float* __restrict__ Cc, int Ndim, int Kdim) {
    uint32_t sb = smem_to_u32(dynsmem);
    const int tid = threadIdx.x;
    const int wid = tid >> 5;
    const int lane = tid & 31;
    const int m0 = blockIdx.y * 128;
    const int n0 = blockIdx.x * 128;
    const int warp_m = (wid >> 2) * 64;   // 0 or 64
    const int warp_n = (wid & 3) * 32;    // 0,32,64,96

    const int tsel = tid >> 6;            // 0:Ahi 1:Alo 2:Bhi 3:Blo
    const int u0 = tid & 63;
    const __nv_bfloat16* gbase =
        (tsel == 0) ? Ahi + (size_t)m0 * Kdim :
        (tsel == 1) ? Alo + (size_t)m0 * Kdim :
        (tsel == 2) ? Bhi + (size_t)n0 * Kdim :
                      Blo + (size_t)n0 * Kdim;

    auto fill = [&](int stage, int chunk) {
        const int k0 = chunk << 5;  // *32
        uint32_t so = sb + stage * STAGEB + tsel * OPTILE;
#pragma unroll
        for (int it = 0; it < 8; it++) {
            int w = u0 + it * 64;           // 0..511
            int row = w >> 2, ch = w & 3;
            const void* g = gbase + (size_t)row * Kdim + k0 + ch * 8;
            uint32_t d = so + row * ROWB + ch * 16;
            asm volatile("cp.async.cg.shared.global [%0], [%1], 16;\n" :: "r"(d), "l"(g));
        }
        asm volatile("cp.async.commit_group;\n" ::: "memory");
    };

    float acc[4][4][4];
#pragma unroll
    for (int i = 0; i < 4; i++)
#pragma unroll
        for (int j = 0; j < 4; j++)
#pragma unroll
            for (int e = 0; e < 4; e++) acc[i][j][e] = 0.0f;

    const int NC = Kdim >> 5;
    fill(0, 0);

    // ldmatrix lane addressing (constant across k-steps)
    const int a_row = lane & 15;          // A: rows 0-15 of frag
    const int a_ch = lane >> 4;           // A: k-chunk (16B)
    const int b_row = (lane & 7) + ((lane >> 4) << 3);  // B: +8 for lanes 16-31
    const int b_ch = (lane >> 3) & 1;

    for (int c = 0; c < NC; c++) {
        const int cur = c & 1;
        if (c + 1 < NC) {
            fill(cur ^ 1, c + 1);
            asm volatile("cp.async.wait_group 1;\n" ::: "memory");
        } else {
            asm volatile("cp.async.wait_group 0;\n" ::: "memory");
        }
        __syncthreads();

        uint32_t sAh = sb + cur * STAGEB;
        uint32_t sAl = sAh + OPTILE;
        uint32_t sBh = sAl + OPTILE;
        uint32_t sBl = sBh + OPTILE;

#pragma unroll
        for (int ks = 0; ks < 2; ks++) {
            const int kb = ks * 32 + a_ch * 16;   // byte offset in row for A
            const int kbB = ks * 32 + b_ch * 16;
            uint32_t ah[4][4], al[4][4];
#pragma unroll
            for (int mi = 0; mi < 4; mi++) {
                uint32_t base = (warp_m + mi * 16 + a_row) * ROWB + kb;
                ldsm_x4(ah[mi], sAh + base);
                ldsm_x4(al[mi], sAl + base);
            }
            uint32_t bh[4][2], bl[4][2];
#pragma unroll
            for (int j = 0; j < 2; j++) {
                uint32_t base = (warp_n + j * 16 + b_row) * ROWB + kbB;
                uint32_t t4[4];
                ldsm_x4(t4, sBh + base);
                bh[j * 2][0] = t4[0]; bh[j * 2][1] = t4[1];
                bh[j * 2 + 1][0] = t4[2]; bh[j * 2 + 1][1] = t4[3];
                ldsm_x4(t4, sBl + base);
                bl[j * 2][0] = t4[0]; bl[j * 2][1] = t4[1];
                bl[j * 2 + 1][0] = t4[2]; bl[j * 2 + 1][1] = t4[3];
            }
#pragma unroll
            for (int mi = 0; mi < 4; mi++)
#pragma unroll
                for (int ni = 0; ni < 4; ni++) {
                    mma16816(acc[mi][ni], ah[mi], bh[ni]);
                    mma16816(acc[mi][ni], ah[mi], bl[ni]);
                    mma16816(acc[mi][ni], al[mi], bh[ni]);
                }
        }
        __syncthreads();
    }

    // Epilogue: acc lane map m16n8: d0,d1 -> (row l>>2, col 2(l&3)+{0,1}); d2,d3 -> row+8
#pragma unroll
    for (int mi = 0; mi < 4; mi++) {
#pragma unroll
        for (int ni = 0; ni < 4; ni++) {
            int r = m0 + warp_m + mi * 16 + (lane >> 2);
            int cc = n0 + warp_n + ni * 8 + 2 * (lane & 3);
            *(float2*)(Cc + (size_t)r * Ndim + cc) = make_float2(acc[mi][ni][0], acc[mi][ni][1]);
            *(float2*)(Cc + (size_t)(r + 8) * Ndim + cc) = make_float2(acc[mi][ni][2], acc[mi][ni][3]);
        }
    }
}

// ---------------------------------------------------------------------------
// RoPE (in place, fp32)
// ---------------------------------------------------------------------------
__global__ void rope_kernel(float* __restrict__ buf, int heads, int total) {
    int idx = blockIdx.x * blockDim.x + threadIdx.x;
    if (idx >= total) return;
    int i = idx & 63;
    int h = (idx >> 6) % heads;
    int bt = idx / (64 * heads);
    int t = bt & (T_ - 1);

    float inv = powf(10000.0f, -(float)(2 * i) / 128.0f);
    float ang = (float)t * inv;
    float s, c;
    sincosf(ang, &s, &c);

    float* p = buf + ((size_t)bt * heads + h) * 128;
    float x1 = p[i];
    float x2 = p[i + 64];
    p[i]      = x1 * c - x2 * s;
    p[i + 64] = x2 * c + x1 * s;
}

// ---------------------------------------------------------------------------
// Flash attention (fp32), float4-vectorized score loop
// ---------------------------------------------------------------------------
#define BQ 32
#define TK 32
#define KS_STRIDE 132

__global__ __launch_bounds__(256)
void attn_kernel(const int* __restrict__ seq_lengths) {
    float* smemf = (float*)dynsmem;
    float* Qs = smemf;                      // [32][128]
    float* Ks = Qs + BQ * 128;              // [32][132]
    float* Vs = Ks + TK * KS_STRIDE;        // [32][128]

    const int b = blockIdx.z;
    const int h = blockIdx.y;
    const int q0 = blockIdx.x * BQ;
    const int hk = h >> 2;
    const int tid = threadIdx.x;
    const int warp = tid >> 5;
    const int lane = tid & 31;
    const int seqlen = seq_lengths[b];

    {
        int r = tid >> 3;
        int c0 = (tid & 7) * 16;
        const float* src = g_q + ((size_t)(b * T_ + q0 + r)) * C_ + h * 128 + c0;
        float* dst = Qs + r * 128 + c0;
#pragma unroll
        for (int j = 0; j < 16; j += 4) *(float4*)(dst + j) = *(const float4*)(src + j);
    }

    float m[4], l[4], o[4][4];
#pragma unroll
    for (int j = 0; j < 4; j++) {
        m[j] = -1e30f;
        l[j] = 0.0f;
#pragma unroll
        for (int d = 0; d < 4; d++) o[j][d] = 0.0f;
    }

    const int kthi = q0 / TK;
    int ktlo = (q0 > WINDOW_) ? (q0 - WINDOW_) / TK : 0;
    const int extra = (ktlo > 0) ? 1 : 0;
    const int nt = (kthi - ktlo + 1) + extra;

    for (int it = 0; it < nt; it++) {
        const int kt = extra ? ((it == 0) ? 0 : (ktlo + it - 1)) : it;
        const int kbase = kt * TK;

        __syncthreads();
        {
            int r = tid >> 3;
            int c0 = (tid & 7) * 16;
            const float* ksrc = g_k + ((size_t)(b * T_ + kbase + r)) * KVC_ + hk * 128 + c0;
            const float* vsrc = g_v + ((size_t)(b * T_ + kbase + r)) * KVC_ + hk * 128 + c0;
            float* kd = Ks + r * KS_STRIDE + c0;
            float* vd = Vs + r * 128 + c0;
#pragma unroll
            for (int j = 0; j < 16; j += 4) {
                *(float4*)(kd + j) = *(const float4*)(ksrc + j);
                *(float4*)(vd + j) = *(const float4*)(vsrc + j);
            }
        }
        __syncthreads();

        float s[4] = {0.0f, 0.0f, 0.0f, 0.0f};
        {
            const float4* kp = (const float4*)(Ks + lane * KS_STRIDE);
            const float4* qp = (const float4*)(Qs + (warp * 4) * 128);
#pragma unroll 8
            for (int d4 = 0; d4 < 32; d4++) {
                float4 kv = kp[d4];
                float4 a0 = qp[d4];
                float4 a1 = qp[32 + d4];
                float4 a2 = qp[64 + d4];
                float4 a3 = qp[96 + d4];
                s[0] += a0.x * kv.x + a0.y * kv.y + a0.z * kv.z + a0.w * kv.w;
                s[1] += a1.x * kv.x + a1.y * kv.y + a1.z * kv.z + a1.w * kv.w;
                s[2] += a2.x * kv.x + a2.y * kv.y + a2.z * kv.z + a2.w * kv.w;
                s[3] += a3.x * kv.x + a3.y * kv.y + a3.z * kv.z + a3.w * kv.w;
            }
        }

        float pv[4];
#pragma unroll
        for (int j = 0; j < 4; j++) {
            int q = q0 + warp * 4 + j;
            int k = kbase + lane;
            bool ok = (k <= q) && (((q - k) <= WINDOW_) || (k < SINK_));
            float sv = ok ? s[j] * SCALE_ : -1e30f;

            float mx = sv;
#pragma unroll
            for (int off = 16; off > 0; off >>= 1)
                mx = fmaxf(mx, __shfl_xor_sync(0xffffffffu, mx, off));
            float mnew = fmaxf(m[j], mx);
            float p = __expf(sv - mnew);
            float alpha = __expf(m[j] - mnew);

            float ps = p;
#pragma unroll
            for (int off = 16; off > 0; off >>= 1)
                ps += __shfl_xor_sync(0xffffffffu, ps, off);

            l[j] = l[j] * alpha + ps;
            m[j] = mnew;
#pragma unroll
            for (int d = 0; d < 4; d++) o[j][d] *= alpha;
            pv[j] = p;
        }

#pragma unroll 4
        for (int k = 0; k < TK; k++) {
            float4 vv = *(const float4*)(Vs + k * 128 + lane * 4);
            float p0 = __shfl_sync(0xffffffffu, pv[0], k);
            float p1 = __shfl_sync(0xffffffffu, pv[1], k);
            float p2 = __shfl_sync(0xffffffffu, pv[2], k);
            float p3 = __shfl_sync(0xffffffffu, pv[3], k);
            o[0][0] += p0 * vv.x; o[0][1] += p0 * vv.y; o[0][2] += p0 * vv.z; o[0][3] += p0 * vv.w;
            o[1][0] += p1 * vv.x; o[1][1] += p1 * vv.y; o[1][2] += p1 * vv.z; o[1][3] += p1 * vv.w;
            o[2][0] += p2 * vv.x; o[2][1] += p2 * vv.y; o[2][2] += p2 * vv.z; o[2][3] += p2 * vv.w;
            o[3][0] += p3 * vv.x; o[3][1] += p3 * vv.y; o[3][2] += p3 * vv.z; o[3][3] += p3 * vv.w;
        }
    }

#pragma unroll
    for (int j = 0; j < 4; j++) {
        int q = q0 + warp * 4 + j;
        float invl = (q < seqlen) ? (1.0f / l[j]) : 0.0f;
        float* dst = g_y + ((size_t)(b * T_ + q)) * C_ + h * 128 + lane * 4;
        *(float4*)dst = make_float4(o[j][0] * invl, o[j][1] * invl,
                                    o[j][2] * invl, o[j][3] * invl);
    }
}

// ---------------------------------------------------------------------------
// Launch
// ---------------------------------------------------------------------------
extern "C" void kernel_launch(void* const* d_in, const int* in_sizes, int n_in,
                              void* d_out, int out_size) {
    const float* x  = (const float*)d_in[0];
    const float* Wq = (const float*)d_in[1];
    const float* Wk = (const float*)d_in[2];
    const float* Wv = (const float*)d_in[3];
    const float* Wo = (const float*)d_in[4];
    const int* seq_lengths = (const int*)d_in[5];
    float* out = (float*)d_out;

    float *q_ptr, *k_ptr, *v_ptr, *y_ptr;
    cudaGetSymbolAddress((void**)&q_ptr, g_q);
    cudaGetSymbolAddress((void**)&k_ptr, g_k);
    cudaGetSymbolAddress((void**)&v_ptr, g_v);
    cudaGetSymbolAddress((void**)&y_ptr, g_y);
    __nv_bfloat16 *xhi, *xlo, *yhi, *ylo, *wqh, *wql, *wkh, *wkl, *wvh, *wvl, *woh, *wol;
    cudaGetSymbolAddress((void**)&xhi, g_xhi); cudaGetSymbolAddress((void**)&xlo, g_xlo);
    cudaGetSymbolAddress((void**)&yhi, g_yhi); cudaGetSymbolAddress((void**)&ylo, g_ylo);
    cudaGetSymbolAddress((void**)&wqh, g_wqh); cudaGetSymbolAddress((void**)&wql, g_wql);
    cudaGetSymbolAddress((void**)&wkh, g_wkh); cudaGetSymbolAddress((void**)&wkl, g_wkl);
    cudaGetSymbolAddress((void**)&wvh, g_wvh); cudaGetSymbolAddress((void**)&wvl, g_wvl);
    cudaGetSymbolAddress((void**)&woh, g_woh); cudaGetSymbolAddress((void**)&wol, g_wol);

    const int M = B_ * T_;  // 4096

    cudaFuncSetAttribute((const void*)gemm_bf16split_kernel,
                         cudaFuncAttributeMaxDynamicSharedMemorySize, GSMEM_TOTAL);

    // Split x; transpose-split weights
    {
        int n = M * C_;
        split_kernel<<<n / 4 / 256, 256>>>(x, xhi, xlo, n);
        tsplit_kernel<<<dim3(C_ / 32, C_ / 32), dim3(32, 8)>>>(Wq, wqh, wql, C_, C_);
        tsplit_kernel<<<dim3(KVC_ / 32, C_ / 32), dim3(32, 8)>>>(Wk, wkh, wkl, C_, KVC_);
        tsplit_kernel<<<dim3(KVC_ / 32, C_ / 32), dim3(32, 8)>>>(Wv, wvh, wvl, C_, KVC_);
        tsplit_kernel<<<dim3(C_ / 32, C_ / 32), dim3(32, 8)>>>(Wo, woh, wol, C_, C_);
    }

    // QKV projections (HMMA split-bf16)
    gemm_bf16split_kernel<<<dim3(C_ / 128, M / 128), 256, GSMEM_TOTAL>>>(
        xhi, xlo, wqh, wql, q_ptr, C_, C_);
    gemm_bf16split_kernel<<<dim3(KVC_ / 128, M / 128), 256, GSMEM_TOTAL>>>(
        xhi, xlo, wkh, wkl, k_ptr, KVC_, C_);
    gemm_bf16split_kernel<<<dim3(KVC_ / 128, M / 128), 256, GSMEM_TOTAL>>>(
        xhi, xlo, wvh, wvl, v_ptr, KVC_, C_);

    // RoPE
    {
        int total_q = M * H_ * 64;
        int total_k = M * HKV_ * 64;
        rope_kernel<<<(total_q + 255) / 256, 256>>>(q_ptr, H_, total_q);
        rope_kernel<<<(total_k + 255) / 256, 256>>>(k_ptr, HKV_, total_k);
    }

    // Attention
    {
        size_t smem_bytes = (size_t)(BQ * 128 + TK * KS_STRIDE + TK * 128) * sizeof(float);
        cudaFuncSetAttribute((const void*)attn_kernel,
                             cudaFuncAttributeMaxDynamicSharedMemorySize, (int)smem_bytes);
        attn_kernel<<<dim3(T_ / BQ, H_, B_), 256, smem_bytes>>>(seq_lengths);
    }

    // Split y; output projection
    {
        int n = M * C_;
        split_kernel<<<n / 4 / 256, 256>>>(y_ptr, yhi, ylo, n);
        gemm_bf16split_kernel<<<dim3(C_ / 128, M / 128), 256, GSMEM_TOTAL>>>(
            yhi, ylo, woh, wol, out, C_, C_);
    }
}

// round 5
// speedup vs baseline: 3.9810x; 2.3080x over previous
#include <cuda_runtime.h>
#include <cuda_bf16.h>
#include <cuda_fp16.h>
#include <cstdint>
#include <math.h>

#define B_ 2
#define T_ 2048
#define C_ 2048
#define H_ 16
#define HKV_ 4
#define D_ 128
#define WINDOW_ 1024
#define SINK_ 4
#define KVC_ (HKV_ * D_)   // 512
#define SCALE_ 0.08838834764831845f  // 1/sqrt(128)

extern __shared__ char dynsmem[];

__device__ __forceinline__ uint32_t smem_to_u32(const void* p) {
    uint32_t a;
    asm("{ .reg .u64 t; cvta.to.shared.u64 t, %1; cvt.u32.u64 %0, t; }" : "=r"(a) : "l"(p));
    return a;
}

// ---------------------------------------------------------------------------
// Scratch buffers
// ---------------------------------------------------------------------------
__device__ float g_q[B_ * T_ * C_];
__device__ float g_k[B_ * T_ * KVC_];
__device__ float g_v[B_ * T_ * KVC_];
__device__ float g_y[B_ * T_ * C_];

__device__ __half g_qh[B_ * T_ * C_];    // rope'd, scaled, fp16
__device__ __half g_kh[B_ * T_ * KVC_];  // rope'd fp16
__device__ __half g_vh[B_ * T_ * KVC_];  // fp16

__device__ __nv_bfloat16 g_xhi[B_ * T_ * C_], g_xlo[B_ * T_ * C_];
__device__ __nv_bfloat16 g_yhi[B_ * T_ * C_], g_ylo[B_ * T_ * C_];
__device__ __nv_bfloat16 g_wqh[C_ * C_],   g_wql[C_ * C_];
__device__ __nv_bfloat16 g_wkh[KVC_ * C_], g_wkl[KVC_ * C_];
__device__ __nv_bfloat16 g_wvh[KVC_ * C_], g_wvl[KVC_ * C_];
__device__ __nv_bfloat16 g_woh[C_ * C_],   g_wol[C_ * C_];

// ---------------------------------------------------------------------------
// Split: f32 -> (hi, lo) bf16
// ---------------------------------------------------------------------------
__global__ void split_kernel(const float* __restrict__ in,
                             __nv_bfloat16* __restrict__ hi,
                             __nv_bfloat16* __restrict__ lo, int n) {
    int i = (blockIdx.x * blockDim.x + threadIdx.x) * 4;
    if (i >= n) return;
    float4 v = *(const float4*)(in + i);
    __nv_bfloat16 h0 = __float2bfloat16(v.x);
    __nv_bfloat16 h1 = __float2bfloat16(v.y);
    __nv_bfloat16 h2 = __float2bfloat16(v.z);
    __nv_bfloat16 h3 = __float2bfloat16(v.w);
    __nv_bfloat16 l0 = __float2bfloat16(v.x - __bfloat162float(h0));
    __nv_bfloat16 l1 = __float2bfloat16(v.y - __bfloat162float(h1));
    __nv_bfloat16 l2 = __float2bfloat16(v.z - __bfloat162float(h2));
    __nv_bfloat16 l3 = __float2bfloat16(v.w - __bfloat162float(h3));
    *(__nv_bfloat162*)(hi + i)     = __nv_bfloat162(h0, h1);
    *(__nv_bfloat162*)(hi + i + 2) = __nv_bfloat162(h2, h3);
    *(__nv_bfloat162*)(lo + i)     = __nv_bfloat162(l0, l1);
    *(__nv_bfloat162*)(lo + i + 2) = __nv_bfloat162(l2, l3);
}

// ---------------------------------------------------------------------------
// Transpose + split: W [K,N] f32 -> Wt_hi/Wt_lo [N,K] bf16
// ---------------------------------------------------------------------------
__global__ void tsplit_kernel(const float* __restrict__ W,
                              __nv_bfloat16* __restrict__ thi,
                              __nv_bfloat16* __restrict__ tlo, int K, int N) {
    __shared__ float tile[32][33];
    int kb = blockIdx.y * 32, nb = blockIdx.x * 32;
    int tx = threadIdx.x, ty = threadIdx.y;
#pragma unroll
    for (int r = 0; r < 4; r++)
        tile[ty + r * 8][tx] = W[(size_t)(kb + ty + r * 8) * N + nb + tx];
    __syncthreads();
#pragma unroll
    for (int r = 0; r < 4; r++) {
        int n = nb + ty + r * 8;
        int k = kb + tx;
        float v = tile[tx][ty + r * 8];
        __nv_bfloat16 h = __float2bfloat16(v);
        thi[(size_t)n * K + k] = h;
        tlo[(size_t)n * K + k] = __float2bfloat16(v - __bfloat162float(h));
    }
}

// ---------------------------------------------------------------------------
// mma.sync bf16 split GEMM (unchanged from round 4)
// ---------------------------------------------------------------------------
#define ROWB 80
#define OPTILE (128 * ROWB)
#define STAGEB (4 * OPTILE)
#define GSMEM_TOTAL (2 * STAGEB)

__device__ __forceinline__ void ldsm_x4(uint32_t* r, uint32_t addr) {
    asm volatile("ldmatrix.sync.aligned.m8n8.x4.shared.b16 {%0,%1,%2,%3}, [%4];"
                 : "=r"(r[0]), "=r"(r[1]), "=r"(r[2]), "=r"(r[3]) : "r"(addr));
}
__device__ __forceinline__ void ldsm_x4_t(uint32_t* r, uint32_t addr) {
    asm volatile("ldmatrix.sync.aligned.m8n8.x4.trans.shared.b16 {%0,%1,%2,%3}, [%4];"
                 : "=r"(r[0]), "=r"(r[1]), "=r"(r[2]), "=r"(r[3]) : "r"(addr));
}
__device__ __forceinline__ void mma16816(float* d, const uint32_t* a, const uint32_t* b) {
    asm volatile(
        "mma.sync.aligned.m16n8k16.row.col.f32.bf16.bf16.f32 "
        "{%0,%1,%2,%3}, {%4,%5,%6,%7}, {%8,%9}, {%0,%1,%2,%3};"
        : "+f"(d[0]), "+f"(d[1]), "+f"(d[2]), "+f"(d[3])
        : "r"(a[0]), "r"(a[1]), "r"(a[2]), "r"(a[3]), "r"(b[0]), "r"(b[1]));
}
__device__ __forceinline__ void mma16816h(float* d, const uint32_t* a, uint32_t b0, uint32_t b1) {
    asm volatile(
        "mma.sync.aligned.m16n8k16.row.col.f32.f16.f16.f32 "
        "{%0,%1,%2,%3}, {%4,%5,%6,%7}, {%8,%9}, {%0,%1,%2,%3};"
        : "+f"(d[0]), "+f"(d[1]), "+f"(d[2]), "+f"(d[3])
        : "r"(a[0]), "r"(a[1]), "r"(a[2]), "r"(a[3]), "r"(b0), "r"(b1));
}
__device__ __forceinline__ uint32_t packh2(float a, float b) {
    __half2 h = __floats2half2_rn(a, b);
    return *(uint32_t*)&h;
}

__global__ __launch_bounds__(256, 1)
void gemm_bf16split_kernel(const __nv_bfloat16* __restrict__ Ahi,
                           const __nv_bfloat16* __restrict__ Alo,
                           const __nv_bfloat16* __restrict__ Bhi,
                           const __nv_bfloat16* __restrict__ Blo,
                           float* __restrict__ Cc, int Ndim, int Kdim) {
    uint32_t sb = smem_to_u32(dynsmem);
    const int tid = threadIdx.x;
    const int wid = tid >> 5;
    const int lane = tid & 31;
    const int m0 = blockIdx.y * 128;
    const int n0 = blockIdx.x * 128;
    const int warp_m = (wid >> 2) * 64;
    const int warp_n = (wid & 3) * 32;

    const int tsel = tid >> 6;
    const int u0 = tid & 63;
    const __nv_bfloat16* gbase =
        (tsel == 0) ? Ahi + (size_t)m0 * Kdim :
        (tsel == 1) ? Alo + (size_t)m0 * Kdim :
        (tsel == 2) ? Bhi + (size_t)n0 * Kdim :
                      Blo + (size_t)n0 * Kdim;

    auto fill = [&](int stage, int chunk) {
        const int k0 = chunk << 5;
        uint32_t so = sb + stage * STAGEB + tsel * OPTILE;
#pragma unroll
        for (int it = 0; it < 8; it++) {
            int w = u0 + it * 64;
            int row = w >> 2, ch = w & 3;
            const void* g = gbase + (size_t)row * Kdim + k0 + ch * 8;
            uint32_t d = so + row * ROWB + ch * 16;
            asm volatile("cp.async.cg.shared.global [%0], [%1], 16;\n" :: "r"(d), "l"(g));
        }
        asm volatile("cp.async.commit_group;\n" ::: "memory");
    };

    float acc[4][4][4];
#pragma unroll
    for (int i = 0; i < 4; i++)
#pragma unroll
        for (int j = 0; j < 4; j++)
#pragma unroll
            for (int e = 0; e < 4; e++) acc[i][j][e] = 0.0f;

    const int NC = Kdim >> 5;
    fill(0, 0);

    const int a_row = lane & 15;
    const int a_ch = lane >> 4;
    const int b_row = (lane & 7) + ((lane >> 4) << 3);
    const int b_ch = (lane >> 3) & 1;

    for (int c = 0; c < NC; c++) {
        const int cur = c & 1;
        if (c + 1 < NC) {
            fill(cur ^ 1, c + 1);
            asm volatile("cp.async.wait_group 1;\n" ::: "memory");
        } else {
            asm volatile("cp.async.wait_group 0;\n" ::: "memory");
        }
        __syncthreads();

        uint32_t sAh = sb + cur * STAGEB;
        uint32_t sAl = sAh + OPTILE;
        uint32_t sBh = sAl + OPTILE;
        uint32_t sBl = sBh + OPTILE;

#pragma unroll
        for (int ks = 0; ks < 2; ks++) {
            const int kb = ks * 32 + a_ch * 16;
            const int kbB = ks * 32 + b_ch * 16;
            uint32_t ah[4][4], al[4][4];
#pragma unroll
            for (int mi = 0; mi < 4; mi++) {
                uint32_t base = (warp_m + mi * 16 + a_row) * ROWB + kb;
                ldsm_x4(ah[mi], sAh + base);
                ldsm_x4(al[mi], sAl + base);
            }
            uint32_t bh[4][2], bl[4][2];
#pragma unroll
            for (int j = 0; j < 2; j++) {
                uint32_t base = (warp_n + j * 16 + b_row) * ROWB + kbB;
                uint32_t t4[4];
                ldsm_x4(t4, sBh + base);
                bh[j * 2][0] = t4[0]; bh[j * 2][1] = t4[1];
                bh[j * 2 + 1][0] = t4[2]; bh[j * 2 + 1][1] = t4[3];
                ldsm_x4(t4, sBl + base);
                bl[j * 2][0] = t4[0]; bl[j * 2][1] = t4[1];
                bl[j * 2 + 1][0] = t4[2]; bl[j * 2 + 1][1] = t4[3];
            }
#pragma unroll
            for (int mi = 0; mi < 4; mi++)
#pragma unroll
                for (int ni = 0; ni < 4; ni++) {
                    mma16816(acc[mi][ni], ah[mi], bh[ni]);
                    mma16816(acc[mi][ni], ah[mi], bl[ni]);
                    mma16816(acc[mi][ni], al[mi], bh[ni]);
                }
        }
        __syncthreads();
    }

#pragma unroll
    for (int mi = 0; mi < 4; mi++) {
#pragma unroll
        for (int ni = 0; ni < 4; ni++) {
            int r = m0 + warp_m + mi * 16 + (lane >> 2);
            int cc = n0 + warp_n + ni * 8 + 2 * (lane & 3);
            *(float2*)(Cc + (size_t)r * Ndim + cc) = make_float2(acc[mi][ni][0], acc[mi][ni][1]);
            *(float2*)(Cc + (size_t)(r + 8) * Ndim + cc) = make_float2(acc[mi][ni][2], acc[mi][ni][3]);
        }
    }
}

// ---------------------------------------------------------------------------
// RoPE f32 -> f16 (optionally scaled)
// ---------------------------------------------------------------------------
__global__ void rope_half_kernel(const float* __restrict__ src, __half* __restrict__ dst,
                                 int heads, float scale, int total) {
    int idx = blockIdx.x * blockDim.x + threadIdx.x;
    if (idx >= total) return;
    int i = idx & 63;
    int h = (idx >> 6) % heads;
    int bt = idx / (64 * heads);
    int t = bt & (T_ - 1);

    float inv = powf(10000.0f, -(float)(2 * i) / 128.0f);
    float ang = (float)t * inv;
    float s, c;
    sincosf(ang, &s, &c);

    size_t base = ((size_t)bt * heads + h) * 128;
    float x1 = src[base + i];
    float x2 = src[base + i + 64];
    dst[base + i]      = __float2half((x1 * c - x2 * s) * scale);
    dst[base + i + 64] = __float2half((x2 * c + x1 * s) * scale);
}

__global__ void conv_half_kernel(const float* __restrict__ in, __half* __restrict__ out, int n) {
    int i = (blockIdx.x * blockDim.x + threadIdx.x) * 4;
    if (i >= n) return;
    float4 v = *(const float4*)(in + i);
    __half2 a = __floats2half2_rn(v.x, v.y);
    __half2 b = __floats2half2_rn(v.z, v.w);
    *(__half2*)(out + i) = a;
    *(__half2*)(out + i + 2) = b;
}

// ---------------------------------------------------------------------------
// HMMA fp16 flash attention. CTA: 64 queries, 4 warps (m16 each), K-tiles of 64.
// Smem rows padded to 272B for conflict-free ldmatrix.
// ---------------------------------------------------------------------------
#define AROW 136                       // fp16 elems per padded row (272B)
#define ATILE (64 * AROW)              // elems per 64-row tile
#define ASMEM_TOTAL (3 * ATILE * 2)    // Q + K + V = 52224 B

__global__ __launch_bounds__(128, 2)
void attn_hmma_kernel(const int* __restrict__ seq_lengths) {
    __half* sm = (__half*)dynsmem;
    __half* Qs = sm;
    __half* Ks = sm + ATILE;
    __half* Vs = sm + 2 * ATILE;
    const uint32_t qsb = smem_to_u32(Qs);
    const uint32_t ksb = smem_to_u32(Ks);
    const uint32_t vsb = smem_to_u32(Vs);

    const int b = blockIdx.z;
    const int h = blockIdx.y;
    const int q0 = blockIdx.x * 64;
    const int hk = h >> 2;
    const int tid = threadIdx.x;
    const int warp = tid >> 5;
    const int lane = tid & 31;
    const int seqlen = seq_lengths[b];
    const int bT = b * T_;
    const int wq0 = q0 + warp * 16;     // this warp's global query base
    const int r0 = lane >> 2;

    // Load Q tile (64 rows x 256B) via cp.async
#pragma unroll
    for (int i = 0; i < 8; i++) {
        int id = tid + i * 128;
        int row = id >> 4, c = id & 15;
        const void* g = g_qh + (size_t)(bT + q0 + row) * C_ + h * 128 + c * 8;
        uint32_t d = qsb + row * 272 + c * 16;
        asm volatile("cp.async.cg.shared.global [%0], [%1], 16;\n" :: "r"(d), "l"(g));
    }
    asm volatile("cp.async.commit_group;\n" ::: "memory");
    asm volatile("cp.async.wait_group 0;\n" ::: "memory");
    __syncthreads();

    // Q fragments (held in registers for the whole kernel)
    uint32_t qf[8][4];
    {
        const int lrow = (lane & 7) + ((lane & 8) ? 8 : 0);
        const int lcol = (lane & 16) ? 16 : 0;   // bytes
#pragma unroll
        for (int ks = 0; ks < 8; ks++)
            ldsm_x4(qf[ks], qsb + (warp * 16 + lrow) * 272 + ks * 32 + lcol);
    }

    float O[16][4];
#pragma unroll
    for (int t = 0; t < 16; t++)
#pragma unroll
        for (int e = 0; e < 4; e++) O[t][e] = 0.0f;
    float m0r = -1e30f, m1r = -1e30f, l0r = 0.0f, l1r = 0.0f;

    const int kthi = q0 >> 6;
    const int ktlo = (q0 > WINDOW_) ? ((q0 - WINDOW_) >> 6) : 0;
    const int extra = (ktlo > 0) ? 1 : 0;
    const int nt = (kthi - ktlo + 1) + extra;

    const int krowA = (lane & 7) + ((lane & 16) ? 8 : 0);  // K ldsm row part
    const int kcolB = (lane & 8) ? 16 : 0;                 // K ldsm col bytes
    const int vrowA = (lane & 7) + ((lane & 8) ? 8 : 0);   // V ldsm row part
    const int vcolB = (lane & 16) ? 16 : 0;                // V ldsm col bytes

    for (int it = 0; it < nt; it++) {
        const int kt = extra ? ((it == 0) ? 0 : (ktlo + it - 1)) : it;
        const int kbase = kt * 64;

        __syncthreads();  // previous tile's reads done
#pragma unroll
        for (int i = 0; i < 8; i++) {
            int id = tid + i * 128;
            int row = id >> 4, c = id & 15;
            size_t goff = (size_t)(bT + kbase + row) * KVC_ + hk * 128 + c * 8;
            uint32_t soff = row * 272 + c * 16;
            const void* gk = g_kh + goff;
            const void* gv = g_vh + goff;
            asm volatile("cp.async.cg.shared.global [%0], [%1], 16;\n" :: "r"(ksb + soff), "l"(gk));
            asm volatile("cp.async.cg.shared.global [%0], [%1], 16;\n" :: "r"(vsb + soff), "l"(gv));
        }
        asm volatile("cp.async.commit_group;\n" ::: "memory");
        asm volatile("cp.async.wait_group 0;\n" ::: "memory");
        __syncthreads();

        // S = Q K^T  (m16 x n64)
        float S[8][4];
#pragma unroll
        for (int j = 0; j < 8; j++)
#pragma unroll
            for (int e = 0; e < 4; e++) S[j][e] = 0.0f;
#pragma unroll
        for (int ks = 0; ks < 8; ks++) {
#pragma unroll
            for (int np = 0; np < 4; np++) {
                uint32_t kf[4];
                ldsm_x4(kf, ksb + (np * 16 + krowA) * 272 + ks * 32 + kcolB);
                mma16816h(S[2 * np], qf[ks], kf[0], kf[1]);
                mma16816h(S[2 * np + 1], qf[ks], kf[2], kf[3]);
            }
        }

        // Mask (skip if tile fully inside causal window for this warp)
        const bool needmask = !((kbase + 63 <= wq0) && (wq0 + 15 - kbase <= WINDOW_));
        if (needmask) {
#pragma unroll
            for (int j = 0; j < 8; j++) {
                int kk = kbase + j * 8 + 2 * (lane & 3);
#pragma unroll
                for (int e = 0; e < 4; e++) {
                    int q = wq0 + r0 + ((e >= 2) ? 8 : 0);
                    int k = kk + (e & 1);
                    bool ok = (k <= q) && (((q - k) <= WINDOW_) || (k < SINK_));
                    if (!ok) S[j][e] = -1e30f;
                }
            }
        }

        // Online softmax (rows r0 and r0+8)
        float mx0 = -1e30f, mx1 = -1e30f;
#pragma unroll
        for (int j = 0; j < 8; j++) {
            mx0 = fmaxf(mx0, fmaxf(S[j][0], S[j][1]));
            mx1 = fmaxf(mx1, fmaxf(S[j][2], S[j][3]));
        }
        mx0 = fmaxf(mx0, __shfl_xor_sync(0xffffffffu, mx0, 1));
        mx0 = fmaxf(mx0, __shfl_xor_sync(0xffffffffu, mx0, 2));
        mx1 = fmaxf(mx1, __shfl_xor_sync(0xffffffffu, mx1, 1));
        mx1 = fmaxf(mx1, __shfl_xor_sync(0xffffffffu, mx1, 2));

        float mn0 = fmaxf(m0r, mx0);
        float mn1 = fmaxf(m1r, mx1);
        float a0 = __expf(m0r - mn0);
        float a1 = __expf(m1r - mn1);
        float s0 = 0.0f, s1 = 0.0f;
#pragma unroll
        for (int j = 0; j < 8; j++) {
            S[j][0] = __expf(S[j][0] - mn0);
            S[j][1] = __expf(S[j][1] - mn0);
            S[j][2] = __expf(S[j][2] - mn1);
            S[j][3] = __expf(S[j][3] - mn1);
            s0 += S[j][0] + S[j][1];
            s1 += S[j][2] + S[j][3];
        }
        s0 += __shfl_xor_sync(0xffffffffu, s0, 1);
        s0 += __shfl_xor_sync(0xffffffffu, s0, 2);
        s1 += __shfl_xor_sync(0xffffffffu, s1, 1);
        s1 += __shfl_xor_sync(0xffffffffu, s1, 2);

        l0r = l0r * a0 + s0;
        l1r = l1r * a1 + s1;
        m0r = mn0;
        m1r = mn1;
#pragma unroll
        for (int t = 0; t < 16; t++) {
            O[t][0] *= a0; O[t][1] *= a0;
            O[t][2] *= a1; O[t][3] *= a1;
        }

        // O += P V
#pragma unroll
        for (int ks = 0; ks < 4; ks++) {
            uint32_t pa[4];
            pa[0] = packh2(S[2 * ks][0], S[2 * ks][1]);
            pa[1] = packh2(S[2 * ks][2], S[2 * ks][3]);
            pa[2] = packh2(S[2 * ks + 1][0], S[2 * ks + 1][1]);
            pa[3] = packh2(S[2 * ks + 1][2], S[2 * ks + 1][3]);
#pragma unroll
            for (int nq = 0; nq < 8; nq++) {
                uint32_t vf[4];
                ldsm_x4_t(vf, vsb + (ks * 16 + vrowA) * 272 + nq * 32 + vcolB);
                mma16816h(O[2 * nq], pa, vf[0], vf[1]);
                mma16816h(O[2 * nq + 1], pa, vf[2], vf[3]);
            }
        }
    }

    // Epilogue
    const int qr0 = wq0 + r0;
    const int qr1 = qr0 + 8;
    float inv0 = (qr0 < seqlen) ? (1.0f / l0r) : 0.0f;
    float inv1 = (qr1 < seqlen) ? (1.0f / l1r) : 0.0f;
#pragma unroll
    for (int t = 0; t < 16; t++) {
        int col = h * 128 + t * 8 + 2 * (lane & 3);
        *(float2*)(g_y + (size_t)(bT + qr0) * C_ + col) = make_float2(O[t][0] * inv0, O[t][1] * inv0);
        *(float2*)(g_y + (size_t)(bT + qr1) * C_ + col) = make_float2(O[t][2] * inv1, O[t][3] * inv1);
    }
}

// ---------------------------------------------------------------------------
// Launch
// ---------------------------------------------------------------------------
extern "C" void kernel_launch(void* const* d_in, const int* in_sizes, int n_in,
                              void* d_out, int out_size) {
    const float* x  = (const float*)d_in[0];
    const float* Wq = (const float*)d_in[1];
    const float* Wk = (const float*)d_in[2];
    const float* Wv = (const float*)d_in[3];
    const float* Wo = (const float*)d_in[4];
    const int* seq_lengths = (const int*)d_in[5];
    float* out = (float*)d_out;

    float *q_ptr, *k_ptr, *v_ptr, *y_ptr;
    cudaGetSymbolAddress((void**)&q_ptr, g_q);
    cudaGetSymbolAddress((void**)&k_ptr, g_k);
    cudaGetSymbolAddress((void**)&v_ptr, g_v);
    cudaGetSymbolAddress((void**)&y_ptr, g_y);
    __half *qh_ptr, *kh_ptr, *vh_ptr;
    cudaGetSymbolAddress((void**)&qh_ptr, g_qh);
    cudaGetSymbolAddress((void**)&kh_ptr, g_kh);
    cudaGetSymbolAddress((void**)&vh_ptr, g_vh);
    __nv_bfloat16 *xhi, *xlo, *yhi, *ylo, *wqh, *wql, *wkh, *wkl, *wvh, *wvl, *woh, *wol;
    cudaGetSymbolAddress((void**)&xhi, g_xhi); cudaGetSymbolAddress((void**)&xlo, g_xlo);
    cudaGetSymbolAddress((void**)&yhi, g_yhi); cudaGetSymbolAddress((void**)&ylo, g_ylo);
    cudaGetSymbolAddress((void**)&wqh, g_wqh); cudaGetSymbolAddress((void**)&wql, g_wql);
    cudaGetSymbolAddress((void**)&wkh, g_wkh); cudaGetSymbolAddress((void**)&wkl, g_wkl);
    cudaGetSymbolAddress((void**)&wvh, g_wvh); cudaGetSymbolAddress((void**)&wvl, g_wvl);
    cudaGetSymbolAddress((void**)&woh, g_woh); cudaGetSymbolAddress((void**)&wol, g_wol);

    const int M = B_ * T_;  // 4096

    cudaFuncSetAttribute((const void*)gemm_bf16split_kernel,
                         cudaFuncAttributeMaxDynamicSharedMemorySize, GSMEM_TOTAL);
    cudaFuncSetAttribute((const void*)attn_hmma_kernel,
                         cudaFuncAttributeMaxDynamicSharedMemorySize, ASMEM_TOTAL);

    // Split x; transpose-split weights
    {
        int n = M * C_;
        split_kernel<<<n / 4 / 256, 256>>>(x, xhi, xlo, n);
        tsplit_kernel<<<dim3(C_ / 32, C_ / 32), dim3(32, 8)>>>(Wq, wqh, wql, C_, C_);
        tsplit_kernel<<<dim3(KVC_ / 32, C_ / 32), dim3(32, 8)>>>(Wk, wkh, wkl, C_, KVC_);
        tsplit_kernel<<<dim3(KVC_ / 32, C_ / 32), dim3(32, 8)>>>(Wv, wvh, wvl, C_, KVC_);
        tsplit_kernel<<<dim3(C_ / 32, C_ / 32), dim3(32, 8)>>>(Wo, woh, wol, C_, C_);
    }

    // QKV projections (HMMA split-bf16)
    gemm_bf16split_kernel<<<dim3(C_ / 128, M / 128), 256, GSMEM_TOTAL>>>(
        xhi, xlo, wqh, wql, q_ptr, C_, C_);
    gemm_bf16split_kernel<<<dim3(KVC_ / 128, M / 128), 256, GSMEM_TOTAL>>>(
        xhi, xlo, wkh, wkl, k_ptr, KVC_, C_);
    gemm_bf16split_kernel<<<dim3(KVC_ / 128, M / 128), 256, GSMEM_TOTAL>>>(
        xhi, xlo, wvh, wvl, v_ptr, KVC_, C_);

    // RoPE + fp16 conversion (scale folded into q)
    {
        int total_q = M * H_ * 64;
        int total_k = M * HKV_ * 64;
        rope_half_kernel<<<(total_q + 255) / 256, 256>>>(q_ptr, qh_ptr, H_, SCALE_, total_q);
        rope_half_kernel<<<(total_k + 255) / 256, 256>>>(k_ptr, kh_ptr, HKV_, 1.0f, total_k);
        int nv = M * KVC_;
        conv_half_kernel<<<nv / 4 / 256, 256>>>(v_ptr, vh_ptr, nv);
    }

    // Attention (HMMA fp16)
    attn_hmma_kernel<<<dim3(T_ / 64, H_, B_), 128, ASMEM_TOTAL>>>(seq_lengths);

    // Split y; output projection
    {
        int n = M * C_;
        split_kernel<<<n / 4 / 256, 256>>>(y_ptr, yhi, ylo, n);
        gemm_bf16split_kernel<<<dim3(C_ / 128, M / 128), 256, GSMEM_TOTAL>>>(
            yhi, ylo, woh, wol, out, C_, C_);
    }
}

// round 6
// speedup vs baseline: 5.7880x; 1.4539x over previous
#include <cuda_runtime.h>
#include <cuda_bf16.h>
#include <cuda_fp16.h>
#include <cstdint>
#include <math.h>

#define B_ 2
#define T_ 2048
#define C_ 2048
#define H_ 16
#define HKV_ 4
#define D_ 128
#define WINDOW_ 1024
#define SINK_ 4
#define KVC_ (HKV_ * D_)   // 512
#define SCALE_ 0.08838834764831845f  // 1/sqrt(128)

extern __shared__ char dynsmem[];

__device__ __forceinline__ uint32_t smem_to_u32(const void* p) {
    uint32_t a;
    asm("{ .reg .u64 t; cvta.to.shared.u64 t, %1; cvt.u32.u64 %0, t; }" : "=r"(a) : "l"(p));
    return a;
}

// ---------------------------------------------------------------------------
// Scratch buffers
// ---------------------------------------------------------------------------
__device__ float g_q[B_ * T_ * C_];      // fp32 Q (pre-rope)
__device__ float g_k[B_ * T_ * KVC_];
__device__ float g_v[B_ * T_ * KVC_];

__device__ __half g_xh[B_ * T_ * C_];    // fp16 x
__device__ __half g_yh[B_ * T_ * C_];    // fp16 attention output
__device__ __half g_qh[B_ * T_ * C_];    // rope'd, scaled, fp16
__device__ __half g_kh[B_ * T_ * KVC_];  // rope'd fp16
__device__ __half g_vh[B_ * T_ * KVC_];  // fp16

__device__ __half g_wq_h[C_ * C_],   g_wq_l[C_ * C_];     // [N][K] transposed, fp16 hi/lo
__device__ __half g_wk_h[KVC_ * C_], g_wk_l[KVC_ * C_];
__device__ __half g_wv_h[KVC_ * C_], g_wv_l[KVC_ * C_];
__device__ __half g_wo_h[C_ * C_],   g_wo_l[C_ * C_];

// ---------------------------------------------------------------------------
// f32 -> f16 conversion
// ---------------------------------------------------------------------------
__global__ void conv_half_kernel(const float* __restrict__ in, __half* __restrict__ out, int n) {
    int i = (blockIdx.x * blockDim.x + threadIdx.x) * 4;
    if (i >= n) return;
    float4 v = *(const float4*)(in + i);
    *(__half2*)(out + i)     = __floats2half2_rn(v.x, v.y);
    *(__half2*)(out + i + 2) = __floats2half2_rn(v.z, v.w);
}

// ---------------------------------------------------------------------------
// Transpose + fp16 split: W [K,N] f32 -> Wt_hi/Wt_lo [N,K] fp16
// ---------------------------------------------------------------------------
__global__ void tsplit_h_kernel(const float* __restrict__ W,
                                __half* __restrict__ thi,
                                __half* __restrict__ tlo, int K, int N) {
    __shared__ float tile[32][33];
    int kb = blockIdx.y * 32, nb = blockIdx.x * 32;
    int tx = threadIdx.x, ty = threadIdx.y;
#pragma unroll
    for (int r = 0; r < 4; r++)
        tile[ty + r * 8][tx] = W[(size_t)(kb + ty + r * 8) * N + nb + tx];
    __syncthreads();
#pragma unroll
    for (int r = 0; r < 4; r++) {
        int n = nb + ty + r * 8;
        int k = kb + tx;
        float v = tile[tx][ty + r * 8];
        __half h = __float2half(v);
        thi[(size_t)n * K + k] = h;
        tlo[(size_t)n * K + k] = __float2half(v - __half2float(h));
    }
}

// ---------------------------------------------------------------------------
// MMA helpers
// ---------------------------------------------------------------------------
__device__ __forceinline__ void ldsm_x4(uint32_t* r, uint32_t addr) {
    asm volatile("ldmatrix.sync.aligned.m8n8.x4.shared.b16 {%0,%1,%2,%3}, [%4];"
                 : "=r"(r[0]), "=r"(r[1]), "=r"(r[2]), "=r"(r[3]) : "r"(addr));
}
__device__ __forceinline__ void ldsm_x4_t(uint32_t* r, uint32_t addr) {
    asm volatile("ldmatrix.sync.aligned.m8n8.x4.trans.shared.b16 {%0,%1,%2,%3}, [%4];"
                 : "=r"(r[0]), "=r"(r[1]), "=r"(r[2]), "=r"(r[3]) : "r"(addr));
}
__device__ __forceinline__ void mma16816h(float* d, const uint32_t* a, uint32_t b0, uint32_t b1) {
    asm volatile(
        "mma.sync.aligned.m16n8k16.row.col.f32.f16.f16.f32 "
        "{%0,%1,%2,%3}, {%4,%5,%6,%7}, {%8,%9}, {%0,%1,%2,%3};"
        : "+f"(d[0]), "+f"(d[1]), "+f"(d[2]), "+f"(d[3])
        : "r"(a[0]), "r"(a[1]), "r"(a[2]), "r"(a[3]), "r"(b0), "r"(b1));
}
__device__ __forceinline__ uint32_t packh2(float a, float b) {
    __half2 h = __floats2half2_rn(a, b);
    return *(uint32_t*)&h;
}

// ---------------------------------------------------------------------------
// fp16 2-term split GEMM: C[M,N] = A_fp16[M,K] @ (Bhi+Blo)[N,K]^T, fp32 accum.
// CTA 128x128, BK=64, 3-stage cp.async pipeline, 8 warps (2x4), warp 64x32.
// Smem rows 144B (128 data + 16 pad) -> conflict-free ldmatrix.
// ---------------------------------------------------------------------------
#define GROWB 144
#define GTILE (128 * GROWB)        // 18432 B per operand tile
#define GSTAGE (3 * GTILE)         // 55296 B per stage (A, Bh, Bl)
#define GSMEM_TOTAL (3 * GSTAGE)   // 165888 B

__global__ __launch_bounds__(256, 1)
void gemm_fp16split_kernel(const __half* __restrict__ A,
                           const __half* __restrict__ Bhi,
                           const __half* __restrict__ Blo,
                           float* __restrict__ Cc, int Ndim, int Kdim) {
    uint32_t sb = smem_to_u32(dynsmem);
    const int tid = threadIdx.x;
    const int wid = tid >> 5;
    const int lane = tid & 31;
    const int m0 = blockIdx.y * 128;
    const int n0 = blockIdx.x * 128;
    const int warp_m = (wid >> 2) * 64;
    const int warp_n = (wid & 3) * 32;

    const __half* Abase  = A   + (size_t)m0 * Kdim;
    const __half* Bhbase = Bhi + (size_t)n0 * Kdim;
    const __half* Blbase = Blo + (size_t)n0 * Kdim;

    auto fill = [&](int stage, int chunk) {
        const int k0 = chunk << 6;
        uint32_t so = sb + stage * GSTAGE;
#pragma unroll
        for (int it = 0; it < 4; it++) {
            int w = tid + it * 256;         // 0..1023
            int row = w >> 3, ch = w & 7;
            uint32_t d = so + row * GROWB + ch * 16;
            const void* gA = Abase + (size_t)row * Kdim + k0 + ch * 8;
            asm volatile("cp.async.cg.shared.global [%0], [%1], 16;\n" :: "r"(d), "l"(gA));
        }
#pragma unroll
        for (int it = 0; it < 4; it++) {
            int w = tid + it * 256;
            int row = w >> 3, ch = w & 7;
            uint32_t d = so + GTILE + row * GROWB + ch * 16;
            const void* gB = Bhbase + (size_t)row * Kdim + k0 + ch * 8;
            asm volatile("cp.async.cg.shared.global [%0], [%1], 16;\n" :: "r"(d), "l"(gB));
        }
#pragma unroll
        for (int it = 0; it < 4; it++) {
            int w = tid + it * 256;
            int row = w >> 3, ch = w & 7;
            uint32_t d = so + 2 * GTILE + row * GROWB + ch * 16;
            const void* gB = Blbase + (size_t)row * Kdim + k0 + ch * 8;
            asm volatile("cp.async.cg.shared.global [%0], [%1], 16;\n" :: "r"(d), "l"(gB));
        }
    };

    float acc[4][4][4];
#pragma unroll
    for (int i = 0; i < 4; i++)
#pragma unroll
        for (int j = 0; j < 4; j++)
#pragma unroll
            for (int e = 0; e < 4; e++) acc[i][j][e] = 0.0f;

    const int NC = Kdim >> 6;   // chunks of 64

    // Prologue: fill stages 0,1 (NC >= 2 always here)
    fill(0, 0);
    asm volatile("cp.async.commit_group;\n" ::: "memory");
    fill(1, 1);
    asm volatile("cp.async.commit_group;\n" ::: "memory");

    const int a_row = lane & 15;
    const int a_ch = lane >> 4;
    const int b_row = (lane & 7) + ((lane >> 4) << 3);
    const int b_ch = (lane >> 3) & 1;

    for (int c = 0; c < NC; c++) {
        if (c + 2 < NC) fill((c + 2) % 3, c + 2);
        asm volatile("cp.async.commit_group;\n" ::: "memory");
        asm volatile("cp.async.wait_group 2;\n" ::: "memory");
        __syncthreads();

        uint32_t sA  = sb + (c % 3) * GSTAGE;
        uint32_t sBh = sA + GTILE;
        uint32_t sBl = sA + 2 * GTILE;

#pragma unroll
        for (int ks = 0; ks < 4; ks++) {
            uint32_t ah[4][4];
#pragma unroll
            for (int mi = 0; mi < 4; mi++)
                ldsm_x4(ah[mi], sA + (warp_m + mi * 16 + a_row) * GROWB + ks * 32 + a_ch * 16);
            uint32_t bh[4][2], bl[4][2];
#pragma unroll
            for (int j = 0; j < 2; j++) {
                uint32_t base = (warp_n + j * 16 + b_row) * GROWB + ks * 32 + b_ch * 16;
                uint32_t t4[4];
                ldsm_x4(t4, sBh + base);
                bh[j * 2][0] = t4[0]; bh[j * 2][1] = t4[1];
                bh[j * 2 + 1][0] = t4[2]; bh[j * 2 + 1][1] = t4[3];
                ldsm_x4(t4, sBl + base);
                bl[j * 2][0] = t4[0]; bl[j * 2][1] = t4[1];
                bl[j * 2 + 1][0] = t4[2]; bl[j * 2 + 1][1] = t4[3];
            }
#pragma unroll
            for (int mi = 0; mi < 4; mi++)
#pragma unroll
                for (int ni = 0; ni < 4; ni++) {
                    mma16816h(acc[mi][ni], ah[mi], bh[ni][0], bh[ni][1]);
                    mma16816h(acc[mi][ni], ah[mi], bl[ni][0], bl[ni][1]);
                }
        }
        __syncthreads();
    }

#pragma unroll
    for (int mi = 0; mi < 4; mi++) {
#pragma unroll
        for (int ni = 0; ni < 4; ni++) {
            int r = m0 + warp_m + mi * 16 + (lane >> 2);
            int cc = n0 + warp_n + ni * 8 + 2 * (lane & 3);
            *(float2*)(Cc + (size_t)r * Ndim + cc) = make_float2(acc[mi][ni][0], acc[mi][ni][1]);
            *(float2*)(Cc + (size_t)(r + 8) * Ndim + cc) = make_float2(acc[mi][ni][2], acc[mi][ni][3]);
        }
    }
}

// ---------------------------------------------------------------------------
// RoPE f32 -> f16 (optionally scaled)
// ---------------------------------------------------------------------------
__global__ void rope_half_kernel(const float* __restrict__ src, __half* __restrict__ dst,
                                 int heads, float scale, int total) {
    int idx = blockIdx.x * blockDim.x + threadIdx.x;
    if (idx >= total) return;
    int i = idx & 63;
    int h = (idx >> 6) % heads;
    int bt = idx / (64 * heads);
    int t = bt & (T_ - 1);

    float inv = powf(10000.0f, -(float)(2 * i) / 128.0f);
    float ang = (float)t * inv;
    float s, c;
    sincosf(ang, &s, &c);

    size_t base = ((size_t)bt * heads + h) * 128;
    float x1 = src[base + i];
    float x2 = src[base + i + 64];
    dst[base + i]      = __float2half((x1 * c - x2 * s) * scale);
    dst[base + i + 64] = __float2half((x2 * c + x1 * s) * scale);
}

// ---------------------------------------------------------------------------
// HMMA fp16 flash attention (round-5 design; epilogue writes fp16 g_yh)
// ---------------------------------------------------------------------------
#define AROW 136
#define ATILE (64 * AROW)
#define ASMEM_TOTAL (3 * ATILE * 2)

__global__ __launch_bounds__(128, 2)
void attn_hmma_kernel(const int* __restrict__ seq_lengths) {
    __half* sm = (__half*)dynsmem;
    __half* Qs = sm;
    __half* Ks = sm + ATILE;
    __half* Vs = sm + 2 * ATILE;
    const uint32_t qsb = smem_to_u32(Qs);
    const uint32_t ksb = smem_to_u32(Ks);
    const uint32_t vsb = smem_to_u32(Vs);

    const int b = blockIdx.z;
    const int h = blockIdx.y;
    const int q0 = blockIdx.x * 64;
    const int hk = h >> 2;
    const int tid = threadIdx.x;
    const int warp = tid >> 5;
    const int lane = tid & 31;
    const int seqlen = seq_lengths[b];
    const int bT = b * T_;
    const int wq0 = q0 + warp * 16;
    const int r0 = lane >> 2;

#pragma unroll
    for (int i = 0; i < 8; i++) {
        int id = tid + i * 128;
        int row = id >> 4, c = id & 15;
        const void* g = g_qh + (size_t)(bT + q0 + row) * C_ + h * 128 + c * 8;
        uint32_t d = qsb + row * 272 + c * 16;
        asm volatile("cp.async.cg.shared.global [%0], [%1], 16;\n" :: "r"(d), "l"(g));
    }
    asm volatile("cp.async.commit_group;\n" ::: "memory");
    asm volatile("cp.async.wait_group 0;\n" ::: "memory");
    __syncthreads();

    uint32_t qf[8][4];
    {
        const int lrow = (lane & 7) + ((lane & 8) ? 8 : 0);
        const int lcol = (lane & 16) ? 16 : 0;
#pragma unroll
        for (int ks = 0; ks < 8; ks++)
            ldsm_x4(qf[ks], qsb + (warp * 16 + lrow) * 272 + ks * 32 + lcol);
    }

    float O[16][4];
#pragma unroll
    for (int t = 0; t < 16; t++)
#pragma unroll
        for (int e = 0; e < 4; e++) O[t][e] = 0.0f;
    float m0r = -1e30f, m1r = -1e30f, l0r = 0.0f, l1r = 0.0f;

    const int kthi = q0 >> 6;
    const int ktlo = (q0 > WINDOW_) ? ((q0 - WINDOW_) >> 6) : 0;
    const int extra = (ktlo > 0) ? 1 : 0;
    const int nt = (kthi - ktlo + 1) + extra;

    const int krowA = (lane & 7) + ((lane & 16) ? 8 : 0);
    const int kcolB = (lane & 8) ? 16 : 0;
    const int vrowA = (lane & 7) + ((lane & 8) ? 8 : 0);
    const int vcolB = (lane & 16) ? 16 : 0;

    for (int it = 0; it < nt; it++) {
        const int kt = extra ? ((it == 0) ? 0 : (ktlo + it - 1)) : it;
        const int kbase = kt * 64;

        __syncthreads();
#pragma unroll
        for (int i = 0; i < 8; i++) {
            int id = tid + i * 128;
            int row = id >> 4, c = id & 15;
            size_t goff = (size_t)(bT + kbase + row) * KVC_ + hk * 128 + c * 8;
            uint32_t soff = row * 272 + c * 16;
            const void* gk = g_kh + goff;
            const void* gv = g_vh + goff;
            asm volatile("cp.async.cg.shared.global [%0], [%1], 16;\n" :: "r"(ksb + soff), "l"(gk));
            asm volatile("cp.async.cg.shared.global [%0], [%1], 16;\n" :: "r"(vsb + soff), "l"(gv));
        }
        asm volatile("cp.async.commit_group;\n" ::: "memory");
        asm volatile("cp.async.wait_group 0;\n" ::: "memory");
        __syncthreads();

        float S[8][4];
#pragma unroll
        for (int j = 0; j < 8; j++)
#pragma unroll
            for (int e = 0; e < 4; e++) S[j][e] = 0.0f;
#pragma unroll
        for (int ks = 0; ks < 8; ks++) {
#pragma unroll
            for (int np = 0; np < 4; np++) {
                uint32_t kf[4];
                ldsm_x4(kf, ksb + (np * 16 + krowA) * 272 + ks * 32 + kcolB);
                mma16816h(S[2 * np], qf[ks], kf[0], kf[1]);
                mma16816h(S[2 * np + 1], qf[ks], kf[2], kf[3]);
            }
        }

        const bool needmask = !((kbase + 63 <= wq0) && (wq0 + 15 - kbase <= WINDOW_));
        if (needmask) {
#pragma unroll
            for (int j = 0; j < 8; j++) {
                int kk = kbase + j * 8 + 2 * (lane & 3);
#pragma unroll
                for (int e = 0; e < 4; e++) {
                    int q = wq0 + r0 + ((e >= 2) ? 8 : 0);
                    int k = kk + (e & 1);
                    bool ok = (k <= q) && (((q - k) <= WINDOW_) || (k < SINK_));
                    if (!ok) S[j][e] = -1e30f;
                }
            }
        }

        float mx0 = -1e30f, mx1 = -1e30f;
#pragma unroll
        for (int j = 0; j < 8; j++) {
            mx0 = fmaxf(mx0, fmaxf(S[j][0], S[j][1]));
            mx1 = fmaxf(mx1, fmaxf(S[j][2], S[j][3]));
        }
        mx0 = fmaxf(mx0, __shfl_xor_sync(0xffffffffu, mx0, 1));
        mx0 = fmaxf(mx0, __shfl_xor_sync(0xffffffffu, mx0, 2));
        mx1 = fmaxf(mx1, __shfl_xor_sync(0xffffffffu, mx1, 1));
        mx1 = fmaxf(mx1, __shfl_xor_sync(0xffffffffu, mx1, 2));

        float mn0 = fmaxf(m0r, mx0);
        float mn1 = fmaxf(m1r, mx1);
        float a0 = __expf(m0r - mn0);
        float a1 = __expf(m1r - mn1);
        float s0 = 0.0f, s1 = 0.0f;
#pragma unroll
        for (int j = 0; j < 8; j++) {
            S[j][0] = __expf(S[j][0] - mn0);
            S[j][1] = __expf(S[j][1] - mn0);
            S[j][2] = __expf(S[j][2] - mn1);
            S[j][3] = __expf(S[j][3] - mn1);
            s0 += S[j][0] + S[j][1];
            s1 += S[j][2] + S[j][3];
        }
        s0 += __shfl_xor_sync(0xffffffffu, s0, 1);
        s0 += __shfl_xor_sync(0xffffffffu, s0, 2);
        s1 += __shfl_xor_sync(0xffffffffu, s1, 1);
        s1 += __shfl_xor_sync(0xffffffffu, s1, 2);

        l0r = l0r * a0 + s0;
        l1r = l1r * a1 + s1;
        m0r = mn0;
        m1r = mn1;
#pragma unroll
        for (int t = 0; t < 16; t++) {
            O[t][0] *= a0; O[t][1] *= a0;
            O[t][2] *= a1; O[t][3] *= a1;
        }

#pragma unroll
        for (int ks = 0; ks < 4; ks++) {
            uint32_t pa[4];
            pa[0] = packh2(S[2 * ks][0], S[2 * ks][1]);
            pa[1] = packh2(S[2 * ks][2], S[2 * ks][3]);
            pa[2] = packh2(S[2 * ks + 1][0], S[2 * ks + 1][1]);
            pa[3] = packh2(S[2 * ks + 1][2], S[2 * ks + 1][3]);
#pragma unroll
            for (int nq = 0; nq < 8; nq++) {
                uint32_t vf[4];
                ldsm_x4_t(vf, vsb + (ks * 16 + vrowA) * 272 + nq * 32 + vcolB);
                mma16816h(O[2 * nq], pa, vf[0], vf[1]);
                mma16816h(O[2 * nq + 1], pa, vf[2], vf[3]);
            }
        }
    }

    const int qr0 = wq0 + r0;
    const int qr1 = qr0 + 8;
    float inv0 = (qr0 < seqlen) ? (1.0f / l0r) : 0.0f;
    float inv1 = (qr1 < seqlen) ? (1.0f / l1r) : 0.0f;
#pragma unroll
    for (int t = 0; t < 16; t++) {
        int col = h * 128 + t * 8 + 2 * (lane & 3);
        *(__half2*)(g_yh + (size_t)(bT + qr0) * C_ + col) =
            __floats2half2_rn(O[t][0] * inv0, O[t][1] * inv0);
        *(__half2*)(g_yh + (size_t)(bT + qr1) * C_ + col) =
            __floats2half2_rn(O[t][2] * inv1, O[t][3] * inv1);
    }
}

// ---------------------------------------------------------------------------
// Launch
// ---------------------------------------------------------------------------
extern "C" void kernel_launch(void* const* d_in, const int* in_sizes, int n_in,
                              void* d_out, int out_size) {
    const float* x  = (const float*)d_in[0];
    const float* Wq = (const float*)d_in[1];
    const float* Wk = (const float*)d_in[2];
    const float* Wv = (const float*)d_in[3];
    const float* Wo = (const float*)d_in[4];
    const int* seq_lengths = (const int*)d_in[5];
    float* out = (float*)d_out;

    float *q_ptr, *k_ptr, *v_ptr;
    cudaGetSymbolAddress((void**)&q_ptr, g_q);
    cudaGetSymbolAddress((void**)&k_ptr, g_k);
    cudaGetSymbolAddress((void**)&v_ptr, g_v);
    __half *xh, *yh, *qh, *kh, *vh;
    cudaGetSymbolAddress((void**)&xh, g_xh);
    cudaGetSymbolAddress((void**)&yh, g_yh);
    cudaGetSymbolAddress((void**)&qh, g_qh);
    cudaGetSymbolAddress((void**)&kh, g_kh);
    cudaGetSymbolAddress((void**)&vh, g_vh);
    __half *wqh, *wql, *wkh, *wkl, *wvh, *wvl, *woh, *wol;
    cudaGetSymbolAddress((void**)&wqh, g_wq_h); cudaGetSymbolAddress((void**)&wql, g_wq_l);
    cudaGetSymbolAddress((void**)&wkh, g_wk_h); cudaGetSymbolAddress((void**)&wkl, g_wk_l);
    cudaGetSymbolAddress((void**)&wvh, g_wv_h); cudaGetSymbolAddress((void**)&wvl, g_wv_l);
    cudaGetSymbolAddress((void**)&woh, g_wo_h); cudaGetSymbolAddress((void**)&wol, g_wo_l);

    const int M = B_ * T_;  // 4096

    cudaFuncSetAttribute((const void*)gemm_fp16split_kernel,
                         cudaFuncAttributeMaxDynamicSharedMemorySize, GSMEM_TOTAL);
    cudaFuncSetAttribute((const void*)attn_hmma_kernel,
                         cudaFuncAttributeMaxDynamicSharedMemorySize, ASMEM_TOTAL);

    // Prep: x -> fp16; weights -> transposed fp16 hi/lo
    {
        int n = M * C_;
        conv_half_kernel<<<n / 4 / 256, 256>>>(x, xh, n);
        tsplit_h_kernel<<<dim3(C_ / 32, C_ / 32), dim3(32, 8)>>>(Wq, wqh, wql, C_, C_);
        tsplit_h_kernel<<<dim3(KVC_ / 32, C_ / 32), dim3(32, 8)>>>(Wk, wkh, wkl, C_, KVC_);
        tsplit_h_kernel<<<dim3(KVC_ / 32, C_ / 32), dim3(32, 8)>>>(Wv, wvh, wvl, C_, KVC_);
        tsplit_h_kernel<<<dim3(C_ / 32, C_ / 32), dim3(32, 8)>>>(Wo, woh, wol, C_, C_);
    }

    // QKV projections
    gemm_fp16split_kernel<<<dim3(C_ / 128, M / 128), 256, GSMEM_TOTAL>>>(
        xh, wqh, wql, q_ptr, C_, C_);
    gemm_fp16split_kernel<<<dim3(KVC_ / 128, M / 128), 256, GSMEM_TOTAL>>>(
        xh, wkh, wkl, k_ptr, KVC_, C_);
    gemm_fp16split_kernel<<<dim3(KVC_ / 128, M / 128), 256, GSMEM_TOTAL>>>(
        xh, wvh, wvl, v_ptr, KVC_, C_);

    // RoPE + fp16 conversion
    {
        int total_q = M * H_ * 64;
        int total_k = M * HKV_ * 64;
        rope_half_kernel<<<(total_q + 255) / 256, 256>>>(q_ptr, qh, H_, SCALE_, total_q);
        rope_half_kernel<<<(total_k + 255) / 256, 256>>>(k_ptr, kh, HKV_, 1.0f, total_k);
        int nv = M * KVC_;
        conv_half_kernel<<<nv / 4 / 256, 256>>>(v_ptr, vh, nv);
    }

    // Attention (writes fp16 g_yh directly)
    attn_hmma_kernel<<<dim3(T_ / 64, H_, B_), 128, ASMEM_TOTAL>>>(seq_lengths);

    // Output projection
    gemm_fp16split_kernel<<<dim3(C_ / 128, M / 128), 256, GSMEM_TOTAL>>>(
        yh, woh, wol, out, C_, C_);
}

// round 7
// speedup vs baseline: 8.2201x; 1.4202x over previous
#include <cuda_runtime.h>
#include <cuda_fp16.h>
#include <cstdint>
#include <math.h>

#define B_ 2
#define T_ 2048
#define C_ 2048
#define H_ 16
#define HKV_ 4
#define D_ 128
#define WINDOW_ 1024
#define SINK_ 4
#define KVC_ (HKV_ * D_)   // 512
#define QKVC_ (C_ + 2 * KVC_)  // 3072 packed q|k|v row
#define SCALE_ 0.08838834764831845f  // 1/sqrt(128)

extern __shared__ char dynsmem[];

__device__ __forceinline__ uint32_t smem_to_u32(const void* p) {
    uint32_t a;
    asm("{ .reg .u64 t; cvta.to.shared.u64 t, %1; cvt.u32.u64 %0, t; }" : "=r"(a) : "l"(p));
    return a;
}

// ---------------------------------------------------------------------------
// Scratch buffers
// ---------------------------------------------------------------------------
__device__ __half g_xh[B_ * T_ * C_];        // fp16 x
__device__ __half g_qkv[B_ * T_ * QKVC_];    // fp16 packed q|k|v (rope'd in place)
__device__ __half g_yh[B_ * T_ * C_];        // fp16 attention output
__device__ __half g_wqkv[QKVC_ * C_];        // [3072][2048] packed transposed weights
__device__ __half g_wo[C_ * C_];             // [2048][2048] transposed Wo

// ---------------------------------------------------------------------------
// f32 -> f16 conversion
// ---------------------------------------------------------------------------
__global__ void conv_half_kernel(const float* __restrict__ in, __half* __restrict__ out, int n) {
    int i = (blockIdx.x * blockDim.x + threadIdx.x) * 4;
    if (i >= n) return;
    float4 v = *(const float4*)(in + i);
    *(__half2*)(out + i)     = __floats2half2_rn(v.x, v.y);
    *(__half2*)(out + i + 2) = __floats2half2_rn(v.z, v.w);
}

// ---------------------------------------------------------------------------
// Transpose: W [K,N] f32 -> dst [N,K] fp16 (dst pre-offset to target rows)
// ---------------------------------------------------------------------------
__global__ void transp_h_kernel(const float* __restrict__ W,
                                __half* __restrict__ dst, int K, int N) {
    __shared__ float tile[32][33];
    int kb = blockIdx.y * 32, nb = blockIdx.x * 32;
    int tx = threadIdx.x, ty = threadIdx.y;
#pragma unroll
    for (int r = 0; r < 4; r++)
        tile[ty + r * 8][tx] = W[(size_t)(kb + ty + r * 8) * N + nb + tx];
    __syncthreads();
#pragma unroll
    for (int r = 0; r < 4; r++) {
        int n = nb + ty + r * 8;
        int k = kb + tx;
        dst[(size_t)n * K + k] = __float2half(tile[tx][ty + r * 8]);
    }
}

// ---------------------------------------------------------------------------
// MMA helpers
// ---------------------------------------------------------------------------
__device__ __forceinline__ void ldsm_x4(uint32_t* r, uint32_t addr) {
    asm volatile("ldmatrix.sync.aligned.m8n8.x4.shared.b16 {%0,%1,%2,%3}, [%4];"
                 : "=r"(r[0]), "=r"(r[1]), "=r"(r[2]), "=r"(r[3]) : "r"(addr));
}
__device__ __forceinline__ void ldsm_x4_t(uint32_t* r, uint32_t addr) {
    asm volatile("ldmatrix.sync.aligned.m8n8.x4.trans.shared.b16 {%0,%1,%2,%3}, [%4];"
                 : "=r"(r[0]), "=r"(r[1]), "=r"(r[2]), "=r"(r[3]) : "r"(addr));
}
__device__ __forceinline__ void mma16816h(float* d, const uint32_t* a, uint32_t b0, uint32_t b1) {
    asm volatile(
        "mma.sync.aligned.m16n8k16.row.col.f32.f16.f16.f32 "
        "{%0,%1,%2,%3}, {%4,%5,%6,%7}, {%8,%9}, {%0,%1,%2,%3};"
        : "+f"(d[0]), "+f"(d[1]), "+f"(d[2]), "+f"(d[3])
        : "r"(a[0]), "r"(a[1]), "r"(a[2]), "r"(a[3]), "r"(b0), "r"(b1));
}
__device__ __forceinline__ uint32_t packh2(float a, float b) {
    __half2 h = __floats2half2_rn(a, b);
    return *(uint32_t*)&h;
}

// ---------------------------------------------------------------------------
// fp16 GEMM: C[M,N] = A[M,K] @ Bt[N,K]^T, fp32 accum.
// CTA 128x128, BK=64, 3-stage cp.async, 8 warps (2x4), warp 64x32.
// HALF_OUT: write fp16 (row stride Ndim) else fp32.
// ---------------------------------------------------------------------------
#define GROWB 144
#define GTILE (128 * GROWB)        // 18432 B per operand tile
#define GSTAGE (2 * GTILE)         // 36864 B per stage (A, B)
#define GSMEM_TOTAL (3 * GSTAGE)   // 110592 B

template <bool HALF_OUT>
__global__ __launch_bounds__(256, 1)
void gemm_fp16_kernel(const __half* __restrict__ A,
                      const __half* __restrict__ Bt,
                      void* __restrict__ Cc, int Ndim, int Kdim) {
    uint32_t sb = smem_to_u32(dynsmem);
    const int tid = threadIdx.x;
    const int wid = tid >> 5;
    const int lane = tid & 31;
    const int m0 = blockIdx.y * 128;
    const int n0 = blockIdx.x * 128;
    const int warp_m = (wid >> 2) * 64;
    const int warp_n = (wid & 3) * 32;

    const __half* Abase = A  + (size_t)m0 * Kdim;
    const __half* Bbase = Bt + (size_t)n0 * Kdim;

    auto fill = [&](int stage, int chunk) {
        const int k0 = chunk << 6;
        uint32_t so = sb + stage * GSTAGE;
#pragma unroll
        for (int it = 0; it < 4; it++) {
            int w = tid + it * 256;
            int row = w >> 3, ch = w & 7;
            uint32_t d = so + row * GROWB + ch * 16;
            const void* gA = Abase + (size_t)row * Kdim + k0 + ch * 8;
            asm volatile("cp.async.cg.shared.global [%0], [%1], 16;\n" :: "r"(d), "l"(gA));
        }
#pragma unroll
        for (int it = 0; it < 4; it++) {
            int w = tid + it * 256;
            int row = w >> 3, ch = w & 7;
            uint32_t d = so + GTILE + row * GROWB + ch * 16;
            const void* gB = Bbase + (size_t)row * Kdim + k0 + ch * 8;
            asm volatile("cp.async.cg.shared.global [%0], [%1], 16;\n" :: "r"(d), "l"(gB));
        }
    };

    float acc[4][4][4];
#pragma unroll
    for (int i = 0; i < 4; i++)
#pragma unroll
        for (int j = 0; j < 4; j++)
#pragma unroll
            for (int e = 0; e < 4; e++) acc[i][j][e] = 0.0f;

    const int NC = Kdim >> 6;

    fill(0, 0);
    asm volatile("cp.async.commit_group;\n" ::: "memory");
    fill(1, 1);
    asm volatile("cp.async.commit_group;\n" ::: "memory");

    const int a_row = lane & 15;
    const int a_ch = lane >> 4;
    const int b_row = (lane & 7) + ((lane >> 4) << 3);
    const int b_ch = (lane >> 3) & 1;

    for (int c = 0; c < NC; c++) {
        if (c + 2 < NC) fill((c + 2) % 3, c + 2);
        asm volatile("cp.async.commit_group;\n" ::: "memory");
        asm volatile("cp.async.wait_group 2;\n" ::: "memory");
        __syncthreads();

        uint32_t sA = sb + (c % 3) * GSTAGE;
        uint32_t sB = sA + GTILE;

#pragma unroll
        for (int ks = 0; ks < 4; ks++) {
            uint32_t ah[4][4];
#pragma unroll
            for (int mi = 0; mi < 4; mi++)
                ldsm_x4(ah[mi], sA + (warp_m + mi * 16 + a_row) * GROWB + ks * 32 + a_ch * 16);
            uint32_t bf[4][2];
#pragma unroll
            for (int j = 0; j < 2; j++) {
                uint32_t t4[4];
                ldsm_x4(t4, sB + (warp_n + j * 16 + b_row) * GROWB + ks * 32 + b_ch * 16);
                bf[j * 2][0] = t4[0]; bf[j * 2][1] = t4[1];
                bf[j * 2 + 1][0] = t4[2]; bf[j * 2 + 1][1] = t4[3];
            }
#pragma unroll
            for (int mi = 0; mi < 4; mi++)
#pragma unroll
                for (int ni = 0; ni < 4; ni++)
                    mma16816h(acc[mi][ni], ah[mi], bf[ni][0], bf[ni][1]);
        }
        __syncthreads();
    }

#pragma unroll
    for (int mi = 0; mi < 4; mi++) {
#pragma unroll
        for (int ni = 0; ni < 4; ni++) {
            int r = m0 + warp_m + mi * 16 + (lane >> 2);
            int cc = n0 + warp_n + ni * 8 + 2 * (lane & 3);
            if (HALF_OUT) {
                __half* C = (__half*)Cc;
                *(__half2*)(C + (size_t)r * Ndim + cc) =
                    __floats2half2_rn(acc[mi][ni][0], acc[mi][ni][1]);
                *(__half2*)(C + (size_t)(r + 8) * Ndim + cc) =
                    __floats2half2_rn(acc[mi][ni][2], acc[mi][ni][3]);
            } else {
                float* C = (float*)Cc;
                *(float2*)(C + (size_t)r * Ndim + cc) = make_float2(acc[mi][ni][0], acc[mi][ni][1]);
                *(float2*)(C + (size_t)(r + 8) * Ndim + cc) = make_float2(acc[mi][ni][2], acc[mi][ni][3]);
            }
        }
    }
}

// ---------------------------------------------------------------------------
// RoPE in place on packed fp16 buffer. col_off selects q or k region.
// ---------------------------------------------------------------------------
__global__ void rope_inplace_kernel(__half* __restrict__ buf, int col_off,
                                    int heads, float scale, int total) {
    int idx = blockIdx.x * blockDim.x + threadIdx.x;
    if (idx >= total) return;
    int i = idx & 63;
    int h = (idx >> 6) % heads;
    int bt = idx / (64 * heads);
    int t = bt & (T_ - 1);

    float inv = powf(10000.0f, -(float)(2 * i) / 128.0f);
    float ang = (float)t * inv;
    float s, c;
    sincosf(ang, &s, &c);

    __half* p = buf + (size_t)bt * QKVC_ + col_off + h * 128;
    float x1 = __half2float(p[i]);
    float x2 = __half2float(p[i + 64]);
    p[i]      = __float2half((x1 * c - x2 * s) * scale);
    p[i + 64] = __float2half((x2 * c + x1 * s) * scale);
}

// ---------------------------------------------------------------------------
// HMMA fp16 flash attention; reads packed QKV (row stride 3072)
// ---------------------------------------------------------------------------
#define AROW 136
#define ATILE (64 * AROW)
#define ASMEM_TOTAL (3 * ATILE * 2)

__global__ __launch_bounds__(128, 2)
void attn_hmma_kernel(const int* __restrict__ seq_lengths) {
    __half* sm = (__half*)dynsmem;
    __half* Qs = sm;
    __half* Ks = sm + ATILE;
    __half* Vs = sm + 2 * ATILE;
    const uint32_t qsb = smem_to_u32(Qs);
    const uint32_t ksb = smem_to_u32(Ks);
    const uint32_t vsb = smem_to_u32(Vs);

    const int b = blockIdx.z;
    const int h = blockIdx.y;
    const int q0 = blockIdx.x * 64;
    const int hk = h >> 2;
    const int tid = threadIdx.x;
    const int warp = tid >> 5;
    const int lane = tid & 31;
    const int seqlen = seq_lengths[b];
    const int bT = b * T_;
    const int wq0 = q0 + warp * 16;
    const int r0 = lane >> 2;

#pragma unroll
    for (int i = 0; i < 8; i++) {
        int id = tid + i * 128;
        int row = id >> 4, c = id & 15;
        const void* g = g_qkv + (size_t)(bT + q0 + row) * QKVC_ + h * 128 + c * 8;
        uint32_t d = qsb + row * 272 + c * 16;
        asm volatile("cp.async.cg.shared.global [%0], [%1], 16;\n" :: "r"(d), "l"(g));
    }
    asm volatile("cp.async.commit_group;\n" ::: "memory");
    asm volatile("cp.async.wait_group 0;\n" ::: "memory");
    __syncthreads();

    uint32_t qf[8][4];
    {
        const int lrow = (lane & 7) + ((lane & 8) ? 8 : 0);
        const int lcol = (lane & 16) ? 16 : 0;
#pragma unroll
        for (int ks = 0; ks < 8; ks++)
            ldsm_x4(qf[ks], qsb + (warp * 16 + lrow) * 272 + ks * 32 + lcol);
    }

    float O[16][4];
#pragma unroll
    for (int t = 0; t < 16; t++)
#pragma unroll
        for (int e = 0; e < 4; e++) O[t][e] = 0.0f;
    float m0r = -1e30f, m1r = -1e30f, l0r = 0.0f, l1r = 0.0f;

    const int kthi = q0 >> 6;
    const int ktlo = (q0 > WINDOW_) ? ((q0 - WINDOW_) >> 6) : 0;
    const int extra = (ktlo > 0) ? 1 : 0;
    const int nt = (kthi - ktlo + 1) + extra;

    const int krowA = (lane & 7) + ((lane & 16) ? 8 : 0);
    const int kcolB = (lane & 8) ? 16 : 0;
    const int vrowA = (lane & 7) + ((lane & 8) ? 8 : 0);
    const int vcolB = (lane & 16) ? 16 : 0;

    for (int it = 0; it < nt; it++) {
        const int kt = extra ? ((it == 0) ? 0 : (ktlo + it - 1)) : it;
        const int kbase = kt * 64;

        __syncthreads();
#pragma unroll
        for (int i = 0; i < 8; i++) {
            int id = tid + i * 128;
            int row = id >> 4, c = id & 15;
            size_t rbase = (size_t)(bT + kbase + row) * QKVC_ + hk * 128 + c * 8;
            uint32_t soff = row * 272 + c * 16;
            const void* gk = g_qkv + rbase + C_;
            const void* gv = g_qkv + rbase + C_ + KVC_;
            asm volatile("cp.async.cg.shared.global [%0], [%1], 16;\n" :: "r"(ksb + soff), "l"(gk));
            asm volatile("cp.async.cg.shared.global [%0], [%1], 16;\n" :: "r"(vsb + soff), "l"(gv));
        }
        asm volatile("cp.async.commit_group;\n" ::: "memory");
        asm volatile("cp.async.wait_group 0;\n" ::: "memory");
        __syncthreads();

        float S[8][4];
#pragma unroll
        for (int j = 0; j < 8; j++)
#pragma unroll
            for (int e = 0; e < 4; e++) S[j][e] = 0.0f;
#pragma unroll
        for (int ks = 0; ks < 8; ks++) {
#pragma unroll
            for (int np = 0; np < 4; np++) {
                uint32_t kf[4];
                ldsm_x4(kf, ksb + (np * 16 + krowA) * 272 + ks * 32 + kcolB);
                mma16816h(S[2 * np], qf[ks], kf[0], kf[1]);
                mma16816h(S[2 * np + 1], qf[ks], kf[2], kf[3]);
            }
        }

        const bool needmask = !((kbase + 63 <= wq0) && (wq0 + 15 - kbase <= WINDOW_));
        if (needmask) {
#pragma unroll
            for (int j = 0; j < 8; j++) {
                int kk = kbase + j * 8 + 2 * (lane & 3);
#pragma unroll
                for (int e = 0; e < 4; e++) {
                    int q = wq0 + r0 + ((e >= 2) ? 8 : 0);
                    int k = kk + (e & 1);
                    bool ok = (k <= q) && (((q - k) <= WINDOW_) || (k < SINK_));
                    if (!ok) S[j][e] = -1e30f;
                }
            }
        }

        float mx0 = -1e30f, mx1 = -1e30f;
#pragma unroll
        for (int j = 0; j < 8; j++) {
            mx0 = fmaxf(mx0, fmaxf(S[j][0], S[j][1]));
            mx1 = fmaxf(mx1, fmaxf(S[j][2], S[j][3]));
        }
        mx0 = fmaxf(mx0, __shfl_xor_sync(0xffffffffu, mx0, 1));
        mx0 = fmaxf(mx0, __shfl_xor_sync(0xffffffffu, mx0, 2));
        mx1 = fmaxf(mx1, __shfl_xor_sync(0xffffffffu, mx1, 1));
        mx1 = fmaxf(mx1, __shfl_xor_sync(0xffffffffu, mx1, 2));

        float mn0 = fmaxf(m0r, mx0);
        float mn1 = fmaxf(m1r, mx1);
        float a0 = __expf(m0r - mn0);
        float a1 = __expf(m1r - mn1);
        float s0 = 0.0f, s1 = 0.0f;
#pragma unroll
        for (int j = 0; j < 8; j++) {
            S[j][0] = __expf(S[j][0] - mn0);
            S[j][1] = __expf(S[j][1] - mn0);
            S[j][2] = __expf(S[j][2] - mn1);
            S[j][3] = __expf(S[j][3] - mn1);
            s0 += S[j][0] + S[j][1];
            s1 += S[j][2] + S[j][3];
        }
        s0 += __shfl_xor_sync(0xffffffffu, s0, 1);
        s0 += __shfl_xor_sync(0xffffffffu, s0, 2);
        s1 += __shfl_xor_sync(0xffffffffu, s1, 1);
        s1 += __shfl_xor_sync(0xffffffffu, s1, 2);

        l0r = l0r * a0 + s0;
        l1r = l1r * a1 + s1;
        m0r = mn0;
        m1r = mn1;
#pragma unroll
        for (int t = 0; t < 16; t++) {
            O[t][0] *= a0; O[t][1] *= a0;
            O[t][2] *= a1; O[t][3] *= a1;
        }

#pragma unroll
        for (int ks = 0; ks < 4; ks++) {
            uint32_t pa[4];
            pa[0] = packh2(S[2 * ks][0], S[2 * ks][1]);
            pa[1] = packh2(S[2 * ks][2], S[2 * ks][3]);
            pa[2] = packh2(S[2 * ks + 1][0], S[2 * ks + 1][1]);
            pa[3] = packh2(S[2 * ks + 1][2], S[2 * ks + 1][3]);
#pragma unroll
            for (int nq = 0; nq < 8; nq++) {
                uint32_t vf[4];
                ldsm_x4_t(vf, vsb + (ks * 16 + vrowA) * 272 + nq * 32 + vcolB);
                mma16816h(O[2 * nq], pa, vf[0], vf[1]);
                mma16816h(O[2 * nq + 1], pa, vf[2], vf[3]);
            }
        }
    }

    const int qr0 = wq0 + r0;
    const int qr1 = qr0 + 8;
    float inv0 = (qr0 < seqlen) ? (1.0f / l0r) : 0.0f;
    float inv1 = (qr1 < seqlen) ? (1.0f / l1r) : 0.0f;
#pragma unroll
    for (int t = 0; t < 16; t++) {
        int col = h * 128 + t * 8 + 2 * (lane & 3);
        *(__half2*)(g_yh + (size_t)(bT + qr0) * C_ + col) =
            __floats2half2_rn(O[t][0] * inv0, O[t][1] * inv0);
        *(__half2*)(g_yh + (size_t)(bT + qr1) * C_ + col) =
            __floats2half2_rn(O[t][2] * inv1, O[t][3] * inv1);
    }
}

// ---------------------------------------------------------------------------
// Launch
// ---------------------------------------------------------------------------
extern "C" void kernel_launch(void* const* d_in, const int* in_sizes, int n_in,
                              void* d_out, int out_size) {
    const float* x  = (const float*)d_in[0];
    const float* Wq = (const float*)d_in[1];
    const float* Wk = (const float*)d_in[2];
    const float* Wv = (const float*)d_in[3];
    const float* Wo = (const float*)d_in[4];
    const int* seq_lengths = (const int*)d_in[5];
    float* out = (float*)d_out;

    __half *xh, *qkv, *yh, *wqkv, *wo;
    cudaGetSymbolAddress((void**)&xh, g_xh);
    cudaGetSymbolAddress((void**)&qkv, g_qkv);
    cudaGetSymbolAddress((void**)&yh, g_yh);
    cudaGetSymbolAddress((void**)&wqkv, g_wqkv);
    cudaGetSymbolAddress((void**)&wo, g_wo);

    const int M = B_ * T_;  // 4096

    cudaFuncSetAttribute((const void*)gemm_fp16_kernel<true>,
                         cudaFuncAttributeMaxDynamicSharedMemorySize, GSMEM_TOTAL);
    cudaFuncSetAttribute((const void*)gemm_fp16_kernel<false>,
                         cudaFuncAttributeMaxDynamicSharedMemorySize, GSMEM_TOTAL);
    cudaFuncSetAttribute((const void*)attn_hmma_kernel,
                         cudaFuncAttributeMaxDynamicSharedMemorySize, ASMEM_TOTAL);

    // Prep: x -> fp16; weights -> packed transposed fp16
    {
        int n = M * C_;
        conv_half_kernel<<<n / 4 / 256, 256>>>(x, xh, n);
        transp_h_kernel<<<dim3(C_ / 32, C_ / 32), dim3(32, 8)>>>(Wq, wqkv, C_, C_);
        transp_h_kernel<<<dim3(KVC_ / 32, C_ / 32), dim3(32, 8)>>>(Wk, wqkv + (size_t)C_ * C_, C_, KVC_);
        transp_h_kernel<<<dim3(KVC_ / 32, C_ / 32), dim3(32, 8)>>>(Wv, wqkv + (size_t)(C_ + KVC_) * C_, C_, KVC_);
        transp_h_kernel<<<dim3(C_ / 32, C_ / 32), dim3(32, 8)>>>(Wo, wo, C_, C_);
    }

    // Fused QKV projection (fp16 out, packed rows of 3072)
    gemm_fp16_kernel<true><<<dim3(QKVC_ / 128, M / 128), 256, GSMEM_TOTAL>>>(
        xh, wqkv, qkv, QKVC_, C_);

    // RoPE in place (scale folded into q)
    {
        int total_q = M * H_ * 64;
        int total_k = M * HKV_ * 64;
        rope_inplace_kernel<<<(total_q + 255) / 256, 256>>>(qkv, 0, H_, SCALE_, total_q);
        rope_inplace_kernel<<<(total_k + 255) / 256, 256>>>(qkv, C_, HKV_, 1.0f, total_k);
    }

    // Attention
    attn_hmma_kernel<<<dim3(T_ / 64, H_, B_), 128, ASMEM_TOTAL>>>(seq_lengths);

    // Output projection (fp32 out)
    gemm_fp16_kernel<false><<<dim3(C_ / 128, M / 128), 256, GSMEM_TOTAL>>>(
        yh, wo, out, C_, C_);
}

// round 8
// speedup vs baseline: 8.4822x; 1.0319x over previous
#include <cuda_runtime.h>
#include <cuda_fp16.h>
#include <cstdint>
#include <math.h>

#define B_ 2
#define T_ 2048
#define C_ 2048
#define H_ 16
#define HKV_ 4
#define D_ 128
#define WINDOW_ 1024
#define SINK_ 4
#define KVC_ (HKV_ * D_)   // 512
#define QKVC_ (C_ + 2 * KVC_)  // 3072 packed q|k|v row
#define SCALE_ 0.08838834764831845f  // 1/sqrt(128)

extern __shared__ char dynsmem[];

__device__ __forceinline__ uint32_t smem_to_u32(const void* p) {
    uint32_t a;
    asm("{ .reg .u64 t; cvta.to.shared.u64 t, %1; cvt.u32.u64 %0, t; }" : "=r"(a) : "l"(p));
    return a;
}

// ---------------------------------------------------------------------------
// Scratch buffers
// ---------------------------------------------------------------------------
__device__ __half g_xh[B_ * T_ * C_];        // fp16 x
__device__ __half g_qkv[B_ * T_ * QKVC_];    // fp16 packed q|k|v (rope'd in place)
__device__ __half g_yh[B_ * T_ * C_];        // fp16 attention output
__device__ __half g_wqkv[QKVC_ * C_];        // [3072][2048] packed transposed weights
__device__ __half g_wo[C_ * C_];             // [2048][2048] transposed Wo

// ---------------------------------------------------------------------------
// f32 -> f16 conversion
// ---------------------------------------------------------------------------
__global__ void conv_half_kernel(const float* __restrict__ in, __half* __restrict__ out, int n) {
    int i = (blockIdx.x * blockDim.x + threadIdx.x) * 4;
    if (i >= n) return;
    float4 v = *(const float4*)(in + i);
    *(__half2*)(out + i)     = __floats2half2_rn(v.x, v.y);
    *(__half2*)(out + i + 2) = __floats2half2_rn(v.z, v.w);
}

// ---------------------------------------------------------------------------
// Transpose: W [K,N] f32 -> dst [N,K] fp16
// ---------------------------------------------------------------------------
__global__ void transp_h_kernel(const float* __restrict__ W,
                                __half* __restrict__ dst, int K, int N) {
    __shared__ float tile[32][33];
    int kb = blockIdx.y * 32, nb = blockIdx.x * 32;
    int tx = threadIdx.x, ty = threadIdx.y;
#pragma unroll
    for (int r = 0; r < 4; r++)
        tile[ty + r * 8][tx] = W[(size_t)(kb + ty + r * 8) * N + nb + tx];
    __syncthreads();
#pragma unroll
    for (int r = 0; r < 4; r++) {
        int n = nb + ty + r * 8;
        int k = kb + tx;
        dst[(size_t)n * K + k] = __float2half(tile[tx][ty + r * 8]);
    }
}

// ---------------------------------------------------------------------------
// MMA helpers
// ---------------------------------------------------------------------------
__device__ __forceinline__ void ldsm_x4(uint32_t* r, uint32_t addr) {
    asm volatile("ldmatrix.sync.aligned.m8n8.x4.shared.b16 {%0,%1,%2,%3}, [%4];"
                 : "=r"(r[0]), "=r"(r[1]), "=r"(r[2]), "=r"(r[3]) : "r"(addr));
}
__device__ __forceinline__ void ldsm_x4_t(uint32_t* r, uint32_t addr) {
    asm volatile("ldmatrix.sync.aligned.m8n8.x4.trans.shared.b16 {%0,%1,%2,%3}, [%4];"
                 : "=r"(r[0]), "=r"(r[1]), "=r"(r[2]), "=r"(r[3]) : "r"(addr));
}
__device__ __forceinline__ void mma16816h(float* d, const uint32_t* a, uint32_t b0, uint32_t b1) {
    asm volatile(
        "mma.sync.aligned.m16n8k16.row.col.f32.f16.f16.f32 "
        "{%0,%1,%2,%3}, {%4,%5,%6,%7}, {%8,%9}, {%0,%1,%2,%3};"
        : "+f"(d[0]), "+f"(d[1]), "+f"(d[2]), "+f"(d[3])
        : "r"(a[0]), "r"(a[1]), "r"(a[2]), "r"(a[3]), "r"(b0), "r"(b1));
}
__device__ __forceinline__ uint32_t packh2(float a, float b) {
    __half2 h = __floats2half2_rn(a, b);
    return *(uint32_t*)&h;
}

// ---------------------------------------------------------------------------
// fp16 GEMM: C[M,N] = A[M,K] @ Bt[N,K]^T, fp32 accum.
// CTA 128x128, BK=64, 3-stage cp.async, 8 warps (2x4), warp 64x32.
// ---------------------------------------------------------------------------
#define GROWB 144
#define GTILE (128 * GROWB)
#define GSTAGE (2 * GTILE)
#define GSMEM_TOTAL (3 * GSTAGE)

template <bool HALF_OUT>
__global__ __launch_bounds__(256, 1)
void gemm_fp16_kernel(const __half* __restrict__ A,
                      const __half* __restrict__ Bt,
                      void* __restrict__ Cc, int Ndim, int Kdim) {
    uint32_t sb = smem_to_u32(dynsmem);
    const int tid = threadIdx.x;
    const int wid = tid >> 5;
    const int lane = tid & 31;
    const int m0 = blockIdx.y * 128;
    const int n0 = blockIdx.x * 128;
    const int warp_m = (wid >> 2) * 64;
    const int warp_n = (wid & 3) * 32;

    const __half* Abase = A  + (size_t)m0 * Kdim;
    const __half* Bbase = Bt + (size_t)n0 * Kdim;

    auto fill = [&](int stage, int chunk) {
        const int k0 = chunk << 6;
        uint32_t so = sb + stage * GSTAGE;
#pragma unroll
        for (int it = 0; it < 4; it++) {
            int w = tid + it * 256;
            int row = w >> 3, ch = w & 7;
            uint32_t d = so + row * GROWB + ch * 16;
            const void* gA = Abase + (size_t)row * Kdim + k0 + ch * 8;
            asm volatile("cp.async.cg.shared.global [%0], [%1], 16;\n" :: "r"(d), "l"(gA));
        }
#pragma unroll
        for (int it = 0; it < 4; it++) {
            int w = tid + it * 256;
            int row = w >> 3, ch = w & 7;
            uint32_t d = so + GTILE + row * GROWB + ch * 16;
            const void* gB = Bbase + (size_t)row * Kdim + k0 + ch * 8;
            asm volatile("cp.async.cg.shared.global [%0], [%1], 16;\n" :: "r"(d), "l"(gB));
        }
    };

    float acc[4][4][4];
#pragma unroll
    for (int i = 0; i < 4; i++)
#pragma unroll
        for (int j = 0; j < 4; j++)
#pragma unroll
            for (int e = 0; e < 4; e++) acc[i][j][e] = 0.0f;

    const int NC = Kdim >> 6;

    fill(0, 0);
    asm volatile("cp.async.commit_group;\n" ::: "memory");
    fill(1, 1);
    asm volatile("cp.async.commit_group;\n" ::: "memory");

    const int a_row = lane & 15;
    const int a_ch = lane >> 4;
    const int b_row = (lane & 7) + ((lane >> 4) << 3);
    const int b_ch = (lane >> 3) & 1;

    for (int c = 0; c < NC; c++) {
        if (c + 2 < NC) fill((c + 2) % 3, c + 2);
        asm volatile("cp.async.commit_group;\n" ::: "memory");
        asm volatile("cp.async.wait_group 2;\n" ::: "memory");
        __syncthreads();

        uint32_t sA = sb + (c % 3) * GSTAGE;
        uint32_t sB = sA + GTILE;

#pragma unroll
        for (int ks = 0; ks < 4; ks++) {
            uint32_t ah[4][4];
#pragma unroll
            for (int mi = 0; mi < 4; mi++)
                ldsm_x4(ah[mi], sA + (warp_m + mi * 16 + a_row) * GROWB + ks * 32 + a_ch * 16);
            uint32_t bf[4][2];
#pragma unroll
            for (int j = 0; j < 2; j++) {
                uint32_t t4[4];
                ldsm_x4(t4, sB + (warp_n + j * 16 + b_row) * GROWB + ks * 32 + b_ch * 16);
                bf[j * 2][0] = t4[0]; bf[j * 2][1] = t4[1];
                bf[j * 2 + 1][0] = t4[2]; bf[j * 2 + 1][1] = t4[3];
            }
#pragma unroll
            for (int mi = 0; mi < 4; mi++)
#pragma unroll
                for (int ni = 0; ni < 4; ni++)
                    mma16816h(acc[mi][ni], ah[mi], bf[ni][0], bf[ni][1]);
        }
        __syncthreads();
    }

#pragma unroll
    for (int mi = 0; mi < 4; mi++) {
#pragma unroll
        for (int ni = 0; ni < 4; ni++) {
            int r = m0 + warp_m + mi * 16 + (lane >> 2);
            int cc = n0 + warp_n + ni * 8 + 2 * (lane & 3);
            if (HALF_OUT) {
                __half* C = (__half*)Cc;
                *(__half2*)(C + (size_t)r * Ndim + cc) =
                    __floats2half2_rn(acc[mi][ni][0], acc[mi][ni][1]);
                *(__half2*)(C + (size_t)(r + 8) * Ndim + cc) =
                    __floats2half2_rn(acc[mi][ni][2], acc[mi][ni][3]);
            } else {
                float* C = (float*)Cc;
                *(float2*)(C + (size_t)r * Ndim + cc) = make_float2(acc[mi][ni][0], acc[mi][ni][1]);
                *(float2*)(C + (size_t)(r + 8) * Ndim + cc) = make_float2(acc[mi][ni][2], acc[mi][ni][3]);
            }
        }
    }
}

// ---------------------------------------------------------------------------
// Fused RoPE in place on packed buffer: q heads (scaled) and k heads.
// item space per bt-row: (H_ + HKV_) * 64
// ---------------------------------------------------------------------------
__global__ void rope_fused_kernel(__half* __restrict__ buf, int total) {
    int idx = blockIdx.x * blockDim.x + threadIdx.x;
    if (idx >= total) return;
    int i = idx & 63;
    int hh = (idx >> 6) % (H_ + HKV_);
    int bt = idx / (64 * (H_ + HKV_));
    int t = bt & (T_ - 1);

    float inv = powf(10000.0f, -(float)(2 * i) / 128.0f);
    float ang = (float)t * inv;
    float s, c;
    sincosf(ang, &s, &c);

    const bool isq = hh < H_;
    const float scale = isq ? SCALE_ : 1.0f;
    const int col = isq ? hh * 128 : C_ + (hh - H_) * 128;

    __half* p = buf + (size_t)bt * QKVC_ + col;
    float x1 = __half2float(p[i]);
    float x2 = __half2float(p[i + 64]);
    p[i]      = __float2half((x1 * c - x2 * s) * scale);
    p[i + 64] = __float2half((x2 * c + x1 * s) * scale);
}

// ---------------------------------------------------------------------------
// HMMA fp16 flash attention, double-buffered K/V prefetch.
// Smem: Q + 2x(K,V) tiles of 64x136 fp16.
// ---------------------------------------------------------------------------
#define AROW 136
#define ATILE (64 * AROW)          // elems
#define ATILEB (ATILE * 2)         // bytes = 17408
#define ASMEM_TOTAL (5 * ATILEB)   // 87040

__global__ __launch_bounds__(128, 2)
void attn_hmma_kernel(const int* __restrict__ seq_lengths) {
    const uint32_t sbase = smem_to_u32(dynsmem);
    const uint32_t qsb = sbase;

    const int b = blockIdx.z;
    const int h = blockIdx.y;
    const int q0 = blockIdx.x * 64;
    const int hk = h >> 2;
    const int tid = threadIdx.x;
    const int warp = tid >> 5;
    const int lane = tid & 31;
    const int seqlen = seq_lengths[b];
    const int bT = b * T_;
    const int wq0 = q0 + warp * 16;
    const int r0 = lane >> 2;

    const int kthi = q0 >> 6;
    const int ktlo = (q0 > WINDOW_) ? ((q0 - WINDOW_) >> 6) : 0;
    const int extra = (ktlo > 0) ? 1 : 0;
    const int nt = (kthi - ktlo + 1) + extra;

    auto kt_of = [&](int it) { return extra ? ((it == 0) ? 0 : (ktlo + it - 1)) : it; };

    // Issue KV loads for iteration `it` into buffer `buf` (no commit here)
    auto kv_load = [&](int it, int buf) {
        const int kbase = kt_of(it) * 64;
        const uint32_t kb = sbase + (1 + 2 * buf) * ATILEB;
        const uint32_t vb = sbase + (2 + 2 * buf) * ATILEB;
#pragma unroll
        for (int i = 0; i < 8; i++) {
            int id = tid + i * 128;
            int row = id >> 4, c = id & 15;
            size_t rbase = (size_t)(bT + kbase + row) * QKVC_ + hk * 128 + c * 8;
            uint32_t soff = row * 272 + c * 16;
            const void* gk = g_qkv + rbase + C_;
            const void* gv = g_qkv + rbase + C_ + KVC_;
            asm volatile("cp.async.cg.shared.global [%0], [%1], 16;\n" :: "r"(kb + soff), "l"(gk));
            asm volatile("cp.async.cg.shared.global [%0], [%1], 16;\n" :: "r"(vb + soff), "l"(gv));
        }
    };

    // Prologue: Q (group 0), KV tile 0 into buffer 0 (group 1)
#pragma unroll
    for (int i = 0; i < 8; i++) {
        int id = tid + i * 128;
        int row = id >> 4, c = id & 15;
        const void* g = g_qkv + (size_t)(bT + q0 + row) * QKVC_ + h * 128 + c * 8;
        uint32_t d = qsb + row * 272 + c * 16;
        asm volatile("cp.async.cg.shared.global [%0], [%1], 16;\n" :: "r"(d), "l"(g));
    }
    asm volatile("cp.async.commit_group;\n" ::: "memory");
    kv_load(0, 0);
    asm volatile("cp.async.commit_group;\n" ::: "memory");
    asm volatile("cp.async.wait_group 1;\n" ::: "memory");  // Q done
    __syncthreads();

    // Q fragments (registers, whole kernel)
    uint32_t qf[8][4];
    {
        const int lrow = (lane & 7) + ((lane & 8) ? 8 : 0);
        const int lcol = (lane & 16) ? 16 : 0;
#pragma unroll
        for (int ks = 0; ks < 8; ks++)
            ldsm_x4(qf[ks], qsb + (warp * 16 + lrow) * 272 + ks * 32 + lcol);
    }

    float O[16][4];
#pragma unroll
    for (int t = 0; t < 16; t++)
#pragma unroll
        for (int e = 0; e < 4; e++) O[t][e] = 0.0f;
    float m0r = -1e30f, m1r = -1e30f, l0r = 0.0f, l1r = 0.0f;

    const int krowA = (lane & 7) + ((lane & 16) ? 8 : 0);
    const int kcolB = (lane & 8) ? 16 : 0;
    const int vrowA = (lane & 7) + ((lane & 8) ? 8 : 0);
    const int vcolB = (lane & 16) ? 16 : 0;

    for (int it = 0; it < nt; it++) {
        const int buf = it & 1;
        const int kbase = kt_of(it) * 64;

        if (it + 1 < nt) {
            kv_load(it + 1, buf ^ 1);
            asm volatile("cp.async.commit_group;\n" ::: "memory");
            asm volatile("cp.async.wait_group 1;\n" ::: "memory");  // tile `it` done
        } else {
            asm volatile("cp.async.wait_group 0;\n" ::: "memory");
        }
        __syncthreads();

        const uint32_t ksb = sbase + (1 + 2 * buf) * ATILEB;
        const uint32_t vsb = sbase + (2 + 2 * buf) * ATILEB;

        // S = Q K^T
        float S[8][4];
#pragma unroll
        for (int j = 0; j < 8; j++)
#pragma unroll
            for (int e = 0; e < 4; e++) S[j][e] = 0.0f;
#pragma unroll
        for (int ks = 0; ks < 8; ks++) {
#pragma unroll
            for (int np = 0; np < 4; np++) {
                uint32_t kf[4];
                ldsm_x4(kf, ksb + (np * 16 + krowA) * 272 + ks * 32 + kcolB);
                mma16816h(S[2 * np], qf[ks], kf[0], kf[1]);
                mma16816h(S[2 * np + 1], qf[ks], kf[2], kf[3]);
            }
        }

        const bool needmask = !((kbase + 63 <= wq0) && (wq0 + 15 - kbase <= WINDOW_));
        if (needmask) {
#pragma unroll
            for (int j = 0; j < 8; j++) {
                int kk = kbase + j * 8 + 2 * (lane & 3);
#pragma unroll
                for (int e = 0; e < 4; e++) {
                    int q = wq0 + r0 + ((e >= 2) ? 8 : 0);
                    int k = kk + (e & 1);
                    bool ok = (k <= q) && (((q - k) <= WINDOW_) || (k < SINK_));
                    if (!ok) S[j][e] = -1e30f;
                }
            }
        }

        // Online softmax
        float mx0 = -1e30f, mx1 = -1e30f;
#pragma unroll
        for (int j = 0; j < 8; j++) {
            mx0 = fmaxf(mx0, fmaxf(S[j][0], S[j][1]));
            mx1 = fmaxf(mx1, fmaxf(S[j][2], S[j][3]));
        }
        mx0 = fmaxf(mx0, __shfl_xor_sync(0xffffffffu, mx0, 1));
        mx0 = fmaxf(mx0, __shfl_xor_sync(0xffffffffu, mx0, 2));
        mx1 = fmaxf(mx1, __shfl_xor_sync(0xffffffffu, mx1, 1));
        mx1 = fmaxf(mx1, __shfl_xor_sync(0xffffffffu, mx1, 2));

        float mn0 = fmaxf(m0r, mx0);
        float mn1 = fmaxf(m1r, mx1);
        float a0 = __expf(m0r - mn0);
        float a1 = __expf(m1r - mn1);
        float s0 = 0.0f, s1 = 0.0f;
#pragma unroll
        for (int j = 0; j < 8; j++) {
            S[j][0] = __expf(S[j][0] - mn0);
            S[j][1] = __expf(S[j][1] - mn0);
            S[j][2] = __expf(S[j][2] - mn1);
            S[j][3] = __expf(S[j][3] - mn1);
            s0 += S[j][0] + S[j][1];
            s1 += S[j][2] + S[j][3];
        }
        s0 += __shfl_xor_sync(0xffffffffu, s0, 1);
        s0 += __shfl_xor_sync(0xffffffffu, s0, 2);
        s1 += __shfl_xor_sync(0xffffffffu, s1, 1);
        s1 += __shfl_xor_sync(0xffffffffu, s1, 2);

        l0r = l0r * a0 + s0;
        l1r = l1r * a1 + s1;
        m0r = mn0;
        m1r = mn1;
#pragma unroll
        for (int t = 0; t < 16; t++) {
            O[t][0] *= a0; O[t][1] *= a0;
            O[t][2] *= a1; O[t][3] *= a1;
        }

        // O += P V
#pragma unroll
        for (int ks = 0; ks < 4; ks++) {
            uint32_t pa[4];
            pa[0] = packh2(S[2 * ks][0], S[2 * ks][1]);
            pa[1] = packh2(S[2 * ks][2], S[2 * ks][3]);
            pa[2] = packh2(S[2 * ks + 1][0], S[2 * ks + 1][1]);
            pa[3] = packh2(S[2 * ks + 1][2], S[2 * ks + 1][3]);
#pragma unroll
            for (int nq = 0; nq < 8; nq++) {
                uint32_t vf[4];
                ldsm_x4_t(vf, vsb + (ks * 16 + vrowA) * 272 + nq * 32 + vcolB);
                mma16816h(O[2 * nq], pa, vf[0], vf[1]);
                mma16816h(O[2 * nq + 1], pa, vf[2], vf[3]);
            }
        }
        __syncthreads();
    }

    const int qr0 = wq0 + r0;
    const int qr1 = qr0 + 8;
    float inv0 = (qr0 < seqlen) ? (1.0f / l0r) : 0.0f;
    float inv1 = (qr1 < seqlen) ? (1.0f / l1r) : 0.0f;
#pragma unroll
    for (int t = 0; t < 16; t++) {
        int col = h * 128 + t * 8 + 2 * (lane & 3);
        *(__half2*)(g_yh + (size_t)(bT + qr0) * C_ + col) =
            __floats2half2_rn(O[t][0] * inv0, O[t][1] * inv0);
        *(__half2*)(g_yh + (size_t)(bT + qr1) * C_ + col) =
            __floats2half2_rn(O[t][2] * inv1, O[t][3] * inv1);
    }
}

// ---------------------------------------------------------------------------
// Launch
// ---------------------------------------------------------------------------
extern "C" void kernel_launch(void* const* d_in, const int* in_sizes, int n_in,
                              void* d_out, int out_size) {
    const float* x  = (const float*)d_in[0];
    const float* Wq = (const float*)d_in[1];
    const float* Wk = (const float*)d_in[2];
    const float* Wv = (const float*)d_in[3];
    const float* Wo = (const float*)d_in[4];
    const int* seq_lengths = (const int*)d_in[5];
    float* out = (float*)d_out;

    __half *xh, *qkv, *yh, *wqkv, *wo;
    cudaGetSymbolAddress((void**)&xh, g_xh);
    cudaGetSymbolAddress((void**)&qkv, g_qkv);
    cudaGetSymbolAddress((void**)&yh, g_yh);
    cudaGetSymbolAddress((void**)&wqkv, g_wqkv);
    cudaGetSymbolAddress((void**)&wo, g_wo);

    const int M = B_ * T_;  // 4096

    cudaFuncSetAttribute((const void*)gemm_fp16_kernel<true>,
                         cudaFuncAttributeMaxDynamicSharedMemorySize, GSMEM_TOTAL);
    cudaFuncSetAttribute((const void*)gemm_fp16_kernel<false>,
                         cudaFuncAttributeMaxDynamicSharedMemorySize, GSMEM_TOTAL);
    cudaFuncSetAttribute((const void*)attn_hmma_kernel,
                         cudaFuncAttributeMaxDynamicSharedMemorySize, ASMEM_TOTAL);

    // Prep
    {
        int n = M * C_;
        conv_half_kernel<<<n / 4 / 256, 256>>>(x, xh, n);
        transp_h_kernel<<<dim3(C_ / 32, C_ / 32), dim3(32, 8)>>>(Wq, wqkv, C_, C_);
        transp_h_kernel<<<dim3(KVC_ / 32, C_ / 32), dim3(32, 8)>>>(Wk, wqkv + (size_t)C_ * C_, C_, KVC_);
        transp_h_kernel<<<dim3(KVC_ / 32, C_ / 32), dim3(32, 8)>>>(Wv, wqkv + (size_t)(C_ + KVC_) * C_, C_, KVC_);
        transp_h_kernel<<<dim3(C_ / 32, C_ / 32), dim3(32, 8)>>>(Wo, wo, C_, C_);
    }

    // Fused QKV projection
    gemm_fp16_kernel<true><<<dim3(QKVC_ / 128, M / 128), 256, GSMEM_TOTAL>>>(
        xh, wqkv, qkv, QKVC_, C_);

    // Fused RoPE (q scaled, k unscaled)
    {
        int total = M * (H_ + HKV_) * 64;
        rope_fused_kernel<<<(total + 255) / 256, 256>>>(qkv, total);
    }

    // Attention (double-buffered K/V)
    attn_hmma_kernel<<<dim3(T_ / 64, H_, B_), 128, ASMEM_TOTAL>>>(seq_lengths);

    // Output projection (fp32 out)
    gemm_fp16_kernel<false><<<dim3(C_ / 128, M / 128), 256, GSMEM_TOTAL>>>(
        yh, wo, out, C_, C_);
}

// round 9
// speedup vs baseline: 8.6146x; 1.0156x over previous
#include <cuda_runtime.h>
#include <cuda_fp16.h>
#include <cstdint>
#include <math.h>

#define B_ 2
#define T_ 2048
#define C_ 2048
#define H_ 16
#define HKV_ 4
#define D_ 128
#define WINDOW_ 1024
#define SINK_ 4
#define KVC_ (HKV_ * D_)   // 512
#define QKVC_ (C_ + 2 * KVC_)  // 3072
#define SCALE_ 0.08838834764831845f

extern __shared__ char dynsmem[];

__device__ __forceinline__ uint32_t smem_to_u32(const void* p) {
    uint32_t a;
    asm("{ .reg .u64 t; cvta.to.shared.u64 t, %1; cvt.u32.u64 %0, t; }" : "=r"(a) : "l"(p));
    return a;
}

// ---------------------------------------------------------------------------
// Scratch buffers
// ---------------------------------------------------------------------------
__device__ __half g_xh[B_ * T_ * C_];        // fp16 x
__device__ __half g_qkv[B_ * T_ * QKVC_];    // fp16 packed q|k|v
__device__ __half g_yh[B_ * T_ * C_];        // fp16 attention output
__device__ __half g_wqkv[C_ * QKVC_];        // [K=2048][N=3072] packed fp16 weights
__device__ __half g_wo[C_ * C_];             // [K=2048][N=2048] fp16 Wo
__device__ float2 g_rope[T_ * 64];           // (cos, sin) per (t, i)

// ---------------------------------------------------------------------------
// f32 -> f16 (contiguous)
// ---------------------------------------------------------------------------
__global__ void conv_half_kernel(const float* __restrict__ in, __half* __restrict__ out, int n) {
    int i = (blockIdx.x * blockDim.x + threadIdx.x) * 4;
    if (i >= n) return;
    float4 v = *(const float4*)(in + i);
    *(__half2*)(out + i)     = __floats2half2_rn(v.x, v.y);
    *(__half2*)(out + i + 2) = __floats2half2_rn(v.z, v.w);
}

// f32 [K][Nsrc] -> fp16 into dst[k][coloff + n] with row stride Ndst
__global__ void conv_half_strided_kernel(const float* __restrict__ in, __half* __restrict__ dst,
                                         int Nsrc, int Ndst, int coloff, int n) {
    int i = (blockIdx.x * blockDim.x + threadIdx.x) * 4;
    if (i >= n) return;
    float4 v = *(const float4*)(in + i);
    int k = i / Nsrc;
    int c = i - k * Nsrc;
    __half* o = dst + (size_t)k * Ndst + coloff + c;
    *(__half2*)o       = __floats2half2_rn(v.x, v.y);
    *(__half2*)(o + 2) = __floats2half2_rn(v.z, v.w);
}

// ---------------------------------------------------------------------------
// RoPE table + apply
// ---------------------------------------------------------------------------
__global__ void rope_table_kernel() {
    int idx = blockIdx.x * blockDim.x + threadIdx.x;
    if (idx >= T_ * 64) return;
    int i = idx & 63;
    int t = idx >> 6;
    float inv = powf(10000.0f, -(float)(2 * i) / 128.0f);
    float ang = (float)t * inv;
    float s, c;
    sincosf(ang, &s, &c);
    g_rope[idx] = make_float2(c, s);
}

__global__ void rope_apply_kernel(__half* __restrict__ buf, int total) {
    int idx = blockIdx.x * blockDim.x + threadIdx.x;
    if (idx >= total) return;
    int i = idx & 63;
    int hh = (idx >> 6) % (H_ + HKV_);
    int bt = idx / (64 * (H_ + HKV_));
    int t = bt & (T_ - 1);

    float2 cs = g_rope[t * 64 + i];

    const bool isq = hh < H_;
    const float scale = isq ? SCALE_ : 1.0f;
    const int col = isq ? hh * 128 : C_ + (hh - H_) * 128;

    __half* p = buf + (size_t)bt * QKVC_ + col;
    float x1 = __half2float(p[i]);
    float x2 = __half2float(p[i + 64]);
    p[i]      = __float2half((x1 * cs.x - x2 * cs.y) * scale);
    p[i + 64] = __float2half((x2 * cs.x + x1 * cs.y) * scale);
}

// ---------------------------------------------------------------------------
// MMA helpers
// ---------------------------------------------------------------------------
__device__ __forceinline__ void ldsm_x4(uint32_t* r, uint32_t addr) {
    asm volatile("ldmatrix.sync.aligned.m8n8.x4.shared.b16 {%0,%1,%2,%3}, [%4];"
                 : "=r"(r[0]), "=r"(r[1]), "=r"(r[2]), "=r"(r[3]) : "r"(addr));
}
__device__ __forceinline__ void ldsm_x4_t(uint32_t* r, uint32_t addr) {
    asm volatile("ldmatrix.sync.aligned.m8n8.x4.trans.shared.b16 {%0,%1,%2,%3}, [%4];"
                 : "=r"(r[0]), "=r"(r[1]), "=r"(r[2]), "=r"(r[3]) : "r"(addr));
}
__device__ __forceinline__ void mma16816h(float* d, const uint32_t* a, uint32_t b0, uint32_t b1) {
    asm volatile(
        "mma.sync.aligned.m16n8k16.row.col.f32.f16.f16.f32 "
        "{%0,%1,%2,%3}, {%4,%5,%6,%7}, {%8,%9}, {%0,%1,%2,%3};"
        : "+f"(d[0]), "+f"(d[1]), "+f"(d[2]), "+f"(d[3])
        : "r"(a[0]), "r"(a[1]), "r"(a[2]), "r"(a[3]), "r"(b0), "r"(b1));
}
__device__ __forceinline__ uint32_t packh2(float a, float b) {
    __half2 h = __floats2half2_rn(a, b);
    return *(uint32_t*)&h;
}

// ---------------------------------------------------------------------------
// fp16 GEMM: C[M,N] = A[M,K] @ B[K,N], fp32 accum. B in NATIVE [K][N] layout,
// loaded with ldmatrix.trans (same pattern as the attention V operand).
// CTA 128x128, BK=64, 3-stage cp.async, 8 warps (2x4), warp 64x32.
// ---------------------------------------------------------------------------
#define GROWA 144                      // A row bytes (128 data + 16 pad)
#define GROWB 272                      // B row bytes (256 data + 16 pad)
#define GTILE_A (128 * GROWA)          // 18432
#define GTILE_B (64 * GROWB)           // 17408
#define GSTAGE (GTILE_A + GTILE_B)     // 35840
#define GSMEM_TOTAL (3 * GSTAGE)       // 107520

template <bool HALF_OUT>
__global__ __launch_bounds__(256, 1)
void gemm_fp16_kernel(const __half* __restrict__ A,
                      const __half* __restrict__ Bm,
                      void* __restrict__ Cc, int Ndim, int Kdim) {
    uint32_t sb = smem_to_u32(dynsmem);
    const int tid = threadIdx.x;
    const int wid = tid >> 5;
    const int lane = tid & 31;
    const int m0 = blockIdx.y * 128;
    const int n0 = blockIdx.x * 128;
    const int warp_m = (wid >> 2) * 64;
    const int warp_n = (wid & 3) * 32;

    const __half* Abase = A + (size_t)m0 * Kdim;
    const __half* Bbase = Bm + n0;

    auto fill = [&](int stage, int chunk) {
        const int k0 = chunk << 6;
        uint32_t so = sb + stage * GSTAGE;
        // A tile: 128 rows x 64 k (128B rows)
#pragma unroll
        for (int it = 0; it < 4; it++) {
            int w = tid + it * 256;
            int row = w >> 3, ch = w & 7;
            uint32_t d = so + row * GROWA + ch * 16;
            const void* gA = Abase + (size_t)row * Kdim + k0 + ch * 8;
            asm volatile("cp.async.cg.shared.global [%0], [%1], 16;\n" :: "r"(d), "l"(gA));
        }
        // B tile: 64 k-rows x 128 n (256B rows), native [K][N]
#pragma unroll
        for (int it = 0; it < 4; it++) {
            int w = tid + it * 256;
            int row = w >> 4, ch = w & 15;
            uint32_t d = so + GTILE_A + row * GROWB + ch * 16;
            const void* gB = Bbase + (size_t)(k0 + row) * Ndim + ch * 8;
            asm volatile("cp.async.cg.shared.global [%0], [%1], 16;\n" :: "r"(d), "l"(gB));
        }
    };

    float acc[4][4][4];
#pragma unroll
    for (int i = 0; i < 4; i++)
#pragma unroll
        for (int j = 0; j < 4; j++)
#pragma unroll
            for (int e = 0; e < 4; e++) acc[i][j][e] = 0.0f;

    const int NC = Kdim >> 6;

    fill(0, 0);
    asm volatile("cp.async.commit_group;\n" ::: "memory");
    fill(1, 1);
    asm volatile("cp.async.commit_group;\n" ::: "memory");

    const int a_row = lane & 15;
    const int a_ch = lane >> 4;
    const int b_row = (lane & 7) + ((lane & 8) ? 8 : 0);   // trans-ldsm k-row part
    const int b_cb = (lane & 16) ? 16 : 0;                 // trans-ldsm col bytes

    for (int c = 0; c < NC; c++) {
        if (c + 2 < NC) fill((c + 2) % 3, c + 2);
        asm volatile("cp.async.commit_group;\n" ::: "memory");
        asm volatile("cp.async.wait_group 2;\n" ::: "memory");
        __syncthreads();

        uint32_t sA = sb + (c % 3) * GSTAGE;
        uint32_t sB = sA + GTILE_A;

#pragma unroll
        for (int ks = 0; ks < 4; ks++) {
            uint32_t ah[4][4];
#pragma unroll
            for (int mi = 0; mi < 4; mi++)
                ldsm_x4(ah[mi], sA + (warp_m + mi * 16 + a_row) * GROWA + ks * 32 + a_ch * 16);
            uint32_t bf[4][2];
#pragma unroll
            for (int j = 0; j < 2; j++) {
                uint32_t t4[4];
                ldsm_x4_t(t4, sB + (ks * 16 + b_row) * GROWB + warp_n * 2 + j * 32 + b_cb);
                bf[j * 2][0] = t4[0]; bf[j * 2][1] = t4[1];
                bf[j * 2 + 1][0] = t4[2]; bf[j * 2 + 1][1] = t4[3];
            }
#pragma unroll
            for (int mi = 0; mi < 4; mi++)
#pragma unroll
                for (int ni = 0; ni < 4; ni++)
                    mma16816h(acc[mi][ni], ah[mi], bf[ni][0], bf[ni][1]);
        }
        __syncthreads();
    }

#pragma unroll
    for (int mi = 0; mi < 4; mi++) {
#pragma unroll
        for (int ni = 0; ni < 4; ni++) {
            int r = m0 + warp_m + mi * 16 + (lane >> 2);
            int cc = n0 + warp_n + ni * 8 + 2 * (lane & 3);
            if (HALF_OUT) {
                __half* C = (__half*)Cc;
                *(__half2*)(C + (size_t)r * Ndim + cc) =
                    __floats2half2_rn(acc[mi][ni][0], acc[mi][ni][1]);
                *(__half2*)(C + (size_t)(r + 8) * Ndim + cc) =
                    __floats2half2_rn(acc[mi][ni][2], acc[mi][ni][3]);
            } else {
                float* C = (float*)Cc;
                *(float2*)(C + (size_t)r * Ndim + cc) = make_float2(acc[mi][ni][0], acc[mi][ni][1]);
                *(float2*)(C + (size_t)(r + 8) * Ndim + cc) = make_float2(acc[mi][ni][2], acc[mi][ni][3]);
            }
        }
    }
}

// ---------------------------------------------------------------------------
// HMMA fp16 flash attention, double-buffered K/V (round-8 design, unchanged)
// ---------------------------------------------------------------------------
#define AROW 136
#define ATILE (64 * AROW)
#define ATILEB (ATILE * 2)
#define ASMEM_TOTAL (5 * ATILEB)

__global__ __launch_bounds__(128, 2)
void attn_hmma_kernel(const int* __restrict__ seq_lengths) {
    const uint32_t sbase = smem_to_u32(dynsmem);
    const uint32_t qsb = sbase;

    const int b = blockIdx.z;
    const int h = blockIdx.y;
    const int q0 = blockIdx.x * 64;
    const int hk = h >> 2;
    const int tid = threadIdx.x;
    const int warp = tid >> 5;
    const int lane = tid & 31;
    const int seqlen = seq_lengths[b];
    const int bT = b * T_;
    const int wq0 = q0 + warp * 16;
    const int r0 = lane >> 2;

    const int kthi = q0 >> 6;
    const int ktlo = (q0 > WINDOW_) ? ((q0 - WINDOW_) >> 6) : 0;
    const int extra = (ktlo > 0) ? 1 : 0;
    const int nt = (kthi - ktlo + 1) + extra;

    auto kt_of = [&](int it) { return extra ? ((it == 0) ? 0 : (ktlo + it - 1)) : it; };

    auto kv_load = [&](int it, int buf) {
        const int kbase = kt_of(it) * 64;
        const uint32_t kb = sbase + (1 + 2 * buf) * ATILEB;
        const uint32_t vb = sbase + (2 + 2 * buf) * ATILEB;
#pragma unroll
        for (int i = 0; i < 8; i++) {
            int id = tid + i * 128;
            int row = id >> 4, c = id & 15;
            size_t rbase = (size_t)(bT + kbase + row) * QKVC_ + hk * 128 + c * 8;
            uint32_t soff = row * 272 + c * 16;
            const void* gk = g_qkv + rbase + C_;
            const void* gv = g_qkv + rbase + C_ + KVC_;
            asm volatile("cp.async.cg.shared.global [%0], [%1], 16;\n" :: "r"(kb + soff), "l"(gk));
            asm volatile("cp.async.cg.shared.global [%0], [%1], 16;\n" :: "r"(vb + soff), "l"(gv));
        }
    };

#pragma unroll
    for (int i = 0; i < 8; i++) {
        int id = tid + i * 128;
        int row = id >> 4, c = id & 15;
        const void* g = g_qkv + (size_t)(bT + q0 + row) * QKVC_ + h * 128 + c * 8;
        uint32_t d = qsb + row * 272 + c * 16;
        asm volatile("cp.async.cg.shared.global [%0], [%1], 16;\n" :: "r"(d), "l"(g));
    }
    asm volatile("cp.async.commit_group;\n" ::: "memory");
    kv_load(0, 0);
    asm volatile("cp.async.commit_group;\n" ::: "memory");
    asm volatile("cp.async.wait_group 1;\n" ::: "memory");
    __syncthreads();

    uint32_t qf[8][4];
    {
        const int lrow = (lane & 7) + ((lane & 8) ? 8 : 0);
        const int lcol = (lane & 16) ? 16 : 0;
#pragma unroll
        for (int ks = 0; ks < 8; ks++)
            ldsm_x4(qf[ks], qsb + (warp * 16 + lrow) * 272 + ks * 32 + lcol);
    }

    float O[16][4];
#pragma unroll
    for (int t = 0; t < 16; t++)
#pragma unroll
        for (int e = 0; e < 4; e++) O[t][e] = 0.0f;
    float m0r = -1e30f, m1r = -1e30f, l0r = 0.0f, l1r = 0.0f;

    const int krowA = (lane & 7) + ((lane & 16) ? 8 : 0);
    const int kcolB = (lane & 8) ? 16 : 0;
    const int vrowA = (lane & 7) + ((lane & 8) ? 8 : 0);
    const int vcolB = (lane & 16) ? 16 : 0;

    for (int it = 0; it < nt; it++) {
        const int buf = it & 1;
        const int kbase = kt_of(it) * 64;

        if (it + 1 < nt) {
            kv_load(it + 1, buf ^ 1);
            asm volatile("cp.async.commit_group;\n" ::: "memory");
            asm volatile("cp.async.wait_group 1;\n" ::: "memory");
        } else {
            asm volatile("cp.async.wait_group 0;\n" ::: "memory");
        }
        __syncthreads();

        const uint32_t ksb = sbase + (1 + 2 * buf) * ATILEB;
        const uint32_t vsb = sbase + (2 + 2 * buf) * ATILEB;

        float S[8][4];
#pragma unroll
        for (int j = 0; j < 8; j++)
#pragma unroll
            for (int e = 0; e < 4; e++) S[j][e] = 0.0f;
#pragma unroll
        for (int ks = 0; ks < 8; ks++) {
#pragma unroll
            for (int np = 0; np < 4; np++) {
                uint32_t kf[4];
                ldsm_x4(kf, ksb + (np * 16 + krowA) * 272 + ks * 32 + kcolB);
                mma16816h(S[2 * np], qf[ks], kf[0], kf[1]);
                mma16816h(S[2 * np + 1], qf[ks], kf[2], kf[3]);
            }
        }

        const bool needmask = !((kbase + 63 <= wq0) && (wq0 + 15 - kbase <= WINDOW_));
        if (needmask) {
#pragma unroll
            for (int j = 0; j < 8; j++) {
                int kk = kbase + j * 8 + 2 * (lane & 3);
#pragma unroll
                for (int e = 0; e < 4; e++) {
                    int q = wq0 + r0 + ((e >= 2) ? 8 : 0);
                    int k = kk + (e & 1);
                    bool ok = (k <= q) && (((q - k) <= WINDOW_) || (k < SINK_));
                    if (!ok) S[j][e] = -1e30f;
                }
            }
        }

        float mx0 = -1e30f, mx1 = -1e30f;
#pragma unroll
        for (int j = 0; j < 8; j++) {
            mx0 = fmaxf(mx0, fmaxf(S[j][0], S[j][1]));
            mx1 = fmaxf(mx1, fmaxf(S[j][2], S[j][3]));
        }
        mx0 = fmaxf(mx0, __shfl_xor_sync(0xffffffffu, mx0, 1));
        mx0 = fmaxf(mx0, __shfl_xor_sync(0xffffffffu, mx0, 2));
        mx1 = fmaxf(mx1, __shfl_xor_sync(0xffffffffu, mx1, 1));
        mx1 = fmaxf(mx1, __shfl_xor_sync(0xffffffffu, mx1, 2));

        float mn0 = fmaxf(m0r, mx0);
        float mn1 = fmaxf(m1r, mx1);
        float a0 = __expf(m0r - mn0);
        float a1 = __expf(m1r - mn1);
        float s0 = 0.0f, s1 = 0.0f;
#pragma unroll
        for (int j = 0; j < 8; j++) {
            S[j][0] = __expf(S[j][0] - mn0);
            S[j][1] = __expf(S[j][1] - mn0);
            S[j][2] = __expf(S[j][2] - mn1);
            S[j][3] = __expf(S[j][3] - mn1);
            s0 += S[j][0] + S[j][1];
            s1 += S[j][2] + S[j][3];
        }
        s0 += __shfl_xor_sync(0xffffffffu, s0, 1);
        s0 += __shfl_xor_sync(0xffffffffu, s0, 2);
        s1 += __shfl_xor_sync(0xffffffffu, s1, 1);
        s1 += __shfl_xor_sync(0xffffffffu, s1, 2);

        l0r = l0r * a0 + s0;
        l1r = l1r * a1 + s1;
        m0r = mn0;
        m1r = mn1;
#pragma unroll
        for (int t = 0; t < 16; t++) {
            O[t][0] *= a0; O[t][1] *= a0;
            O[t][2] *= a1; O[t][3] *= a1;
        }

#pragma unroll
        for (int ks = 0; ks < 4; ks++) {
            uint32_t pa[4];
            pa[0] = packh2(S[2 * ks][0], S[2 * ks][1]);
            pa[1] = packh2(S[2 * ks][2], S[2 * ks][3]);
            pa[2] = packh2(S[2 * ks + 1][0], S[2 * ks + 1][1]);
            pa[3] = packh2(S[2 * ks + 1][2], S[2 * ks + 1][3]);
#pragma unroll
            for (int nq = 0; nq < 8; nq++) {
                uint32_t vf[4];
                ldsm_x4_t(vf, vsb + (ks * 16 + vrowA) * 272 + nq * 32 + vcolB);
                mma16816h(O[2 * nq], pa, vf[0], vf[1]);
                mma16816h(O[2 * nq + 1], pa, vf[2], vf[3]);
            }
        }
        __syncthreads();
    }

    const int qr0 = wq0 + r0;
    const int qr1 = qr0 + 8;
    float inv0 = (qr0 < seqlen) ? (1.0f / l0r) : 0.0f;
    float inv1 = (qr1 < seqlen) ? (1.0f / l1r) : 0.0f;
#pragma unroll
    for (int t = 0; t < 16; t++) {
        int col = h * 128 + t * 8 + 2 * (lane & 3);
        *(__half2*)(g_yh + (size_t)(bT + qr0) * C_ + col) =
            __floats2half2_rn(O[t][0] * inv0, O[t][1] * inv0);
        *(__half2*)(g_yh + (size_t)(bT + qr1) * C_ + col) =
            __floats2half2_rn(O[t][2] * inv1, O[t][3] * inv1);
    }
}

// ---------------------------------------------------------------------------
// Launch
// ---------------------------------------------------------------------------
extern "C" void kernel_launch(void* const* d_in, const int* in_sizes, int n_in,
                              void* d_out, int out_size) {
    const float* x  = (const float*)d_in[0];
    const float* Wq = (const float*)d_in[1];
    const float* Wk = (const float*)d_in[2];
    const float* Wv = (const float*)d_in[3];
    const float* Wo = (const float*)d_in[4];
    const int* seq_lengths = (const int*)d_in[5];
    float* out = (float*)d_out;

    __half *xh, *qkv, *yh, *wqkv, *wo;
    cudaGetSymbolAddress((void**)&xh, g_xh);
    cudaGetSymbolAddress((void**)&qkv, g_qkv);
    cudaGetSymbolAddress((void**)&yh, g_yh);
    cudaGetSymbolAddress((void**)&wqkv, g_wqkv);
    cudaGetSymbolAddress((void**)&wo, g_wo);

    const int M = B_ * T_;  // 4096

    cudaFuncSetAttribute((const void*)gemm_fp16_kernel<true>,
                         cudaFuncAttributeMaxDynamicSharedMemorySize, GSMEM_TOTAL);
    cudaFuncSetAttribute((const void*)gemm_fp16_kernel<false>,
                         cudaFuncAttributeMaxDynamicSharedMemorySize, GSMEM_TOTAL);
    cudaFuncSetAttribute((const void*)attn_hmma_kernel,
                         cudaFuncAttributeMaxDynamicSharedMemorySize, ASMEM_TOTAL);

    // Prep: conversions only (no transposes); rope table
    {
        int n = M * C_;
        conv_half_kernel<<<n / 4 / 256, 256>>>(x, xh, n);
        int nq = C_ * C_, nk = C_ * KVC_;
        conv_half_strided_kernel<<<nq / 4 / 256, 256>>>(Wq, wqkv, C_, QKVC_, 0, nq);
        conv_half_strided_kernel<<<nk / 4 / 256, 256>>>(Wk, wqkv, KVC_, QKVC_, C_, nk);
        conv_half_strided_kernel<<<nk / 4 / 256, 256>>>(Wv, wqkv, KVC_, QKVC_, C_ + KVC_, nk);
        conv_half_kernel<<<nq / 4 / 256, 256>>>(Wo, wo, nq);
        rope_table_kernel<<<(T_ * 64) / 256, 256>>>();
    }

    // Fused QKV projection (B native [K][N])
    gemm_fp16_kernel<true><<<dim3(QKVC_ / 128, M / 128), 256, GSMEM_TOTAL>>>(
        xh, wqkv, qkv, QKVC_, C_);

    // RoPE apply (table-driven)
    {
        int total = M * (H_ + HKV_) * 64;
        rope_apply_kernel<<<(total + 255) / 256, 256>>>(qkv, total);
    }

    // Attention
    attn_hmma_kernel<<<dim3(T_ / 64, H_, B_), 128, ASMEM_TOTAL>>>(seq_lengths);

    // Output projection (fp32 out)
    gemm_fp16_kernel<false><<<dim3(C_ / 128, M / 128), 256, GSMEM_TOTAL>>>(
        yh, wo, out, C_, C_);
}

// round 10
// speedup vs baseline: 8.7176x; 1.0120x over previous
#include <cuda_runtime.h>
#include <cuda_fp16.h>
#include <cstdint>
#include <math.h>

#define B_ 2
#define T_ 2048
#define C_ 2048
#define H_ 16
#define HKV_ 4
#define D_ 128
#define WINDOW_ 1024
#define SINK_ 4
#define KVC_ (HKV_ * D_)   // 512
#define QKVC_ (C_ + 2 * KVC_)  // 3072
#define SCALE_ 0.08838834764831845f

extern __shared__ char dynsmem[];

__device__ __forceinline__ uint32_t smem_to_u32(const void* p) {
    uint32_t a;
    asm("{ .reg .u64 t; cvta.to.shared.u64 t, %1; cvt.u32.u64 %0, t; }" : "=r"(a) : "l"(p));
    return a;
}

// ---------------------------------------------------------------------------
// Scratch buffers
// ---------------------------------------------------------------------------
__device__ __half g_xh[B_ * T_ * C_];        // fp16 x
__device__ __half g_qkv[B_ * T_ * QKVC_];    // fp16 packed q|k|v
__device__ __half g_yh[B_ * T_ * C_];        // fp16 attention output
__device__ __half g_wqkv[C_ * QKVC_];        // [K=2048][N=3072] packed fp16 weights
__device__ __half g_wo[C_ * C_];             // [K=2048][N=2048] fp16 Wo
__device__ float2 g_rope[T_ * 64];           // (cos, sin) per (t, i)

// ---------------------------------------------------------------------------
// f32 -> f16 (contiguous)
// ---------------------------------------------------------------------------
__global__ void conv_half_kernel(const float* __restrict__ in, __half* __restrict__ out, int n) {
    int i = (blockIdx.x * blockDim.x + threadIdx.x) * 4;
    if (i >= n) return;
    float4 v = *(const float4*)(in + i);
    *(__half2*)(out + i)     = __floats2half2_rn(v.x, v.y);
    *(__half2*)(out + i + 2) = __floats2half2_rn(v.z, v.w);
}

// ---------------------------------------------------------------------------
// All four weight conversions in ONE launch.
// Sections (in float4 units): Wq | Wk | Wv (strided into wqkv) | Wo (contig).
// ---------------------------------------------------------------------------
__global__ void conv_weights_kernel(const float* __restrict__ Wq,
                                    const float* __restrict__ Wk,
                                    const float* __restrict__ Wv,
                                    const float* __restrict__ Wo,
                                    __half* __restrict__ wqkv,
                                    __half* __restrict__ wo) {
    const int NQ = C_ * C_ / 4;       // 1048576
    const int NK = C_ * KVC_ / 4;     // 262144
    int i4 = blockIdx.x * blockDim.x + threadIdx.x;
    const float* src;
    __half* dst;
    if (i4 < NQ) {
        int i = i4 * 4;
        int k = i >> 11;              // / C_
        int c = i & (C_ - 1);
        src = Wq + i;
        dst = wqkv + (size_t)k * QKVC_ + c;
    } else if (i4 < NQ + NK) {
        int i = (i4 - NQ) * 4;
        int k = i >> 9;               // / KVC_
        int c = i & (KVC_ - 1);
        src = Wk + i;
        dst = wqkv + (size_t)k * QKVC_ + C_ + c;
    } else if (i4 < NQ + 2 * NK) {
        int i = (i4 - NQ - NK) * 4;
        int k = i >> 9;
        int c = i & (KVC_ - 1);
        src = Wv + i;
        dst = wqkv + (size_t)k * QKVC_ + C_ + KVC_ + c;
    } else if (i4 < 2 * NQ + 2 * NK) {
        int i = (i4 - NQ - 2 * NK) * 4;
        src = Wo + i;
        dst = wo + i;
    } else {
        return;
    }
    float4 v = *(const float4*)src;
    *(__half2*)dst       = __floats2half2_rn(v.x, v.y);
    *(__half2*)(dst + 2) = __floats2half2_rn(v.z, v.w);
}

// ---------------------------------------------------------------------------
// RoPE table + apply
// ---------------------------------------------------------------------------
__global__ void rope_table_kernel() {
    int idx = blockIdx.x * blockDim.x + threadIdx.x;
    if (idx >= T_ * 64) return;
    int i = idx & 63;
    int t = idx >> 6;
    float inv = powf(10000.0f, -(float)(2 * i) / 128.0f);
    float ang = (float)t * inv;
    float s, c;
    sincosf(ang, &s, &c);
    g_rope[idx] = make_float2(c, s);
}

__global__ void rope_apply_kernel(__half* __restrict__ buf, int total) {
    int idx = blockIdx.x * blockDim.x + threadIdx.x;
    if (idx >= total) return;
    int i = idx & 63;
    int hh = (idx >> 6) % (H_ + HKV_);
    int bt = idx / (64 * (H_ + HKV_));
    int t = bt & (T_ - 1);

    float2 cs = g_rope[t * 64 + i];

    const bool isq = hh < H_;
    const float scale = isq ? SCALE_ : 1.0f;
    const int col = isq ? hh * 128 : C_ + (hh - H_) * 128;

    __half* p = buf + (size_t)bt * QKVC_ + col;
    float x1 = __half2float(p[i]);
    float x2 = __half2float(p[i + 64]);
    p[i]      = __float2half((x1 * cs.x - x2 * cs.y) * scale);
    p[i + 64] = __float2half((x2 * cs.x + x1 * cs.y) * scale);
}

// ---------------------------------------------------------------------------
// MMA helpers
// ---------------------------------------------------------------------------
__device__ __forceinline__ void ldsm_x4(uint32_t* r, uint32_t addr) {
    asm volatile("ldmatrix.sync.aligned.m8n8.x4.shared.b16 {%0,%1,%2,%3}, [%4];"
                 : "=r"(r[0]), "=r"(r[1]), "=r"(r[2]), "=r"(r[3]) : "r"(addr));
}
__device__ __forceinline__ void ldsm_x4_t(uint32_t* r, uint32_t addr) {
    asm volatile("ldmatrix.sync.aligned.m8n8.x4.trans.shared.b16 {%0,%1,%2,%3}, [%4];"
                 : "=r"(r[0]), "=r"(r[1]), "=r"(r[2]), "=r"(r[3]) : "r"(addr));
}
__device__ __forceinline__ void mma16816h(float* d, const uint32_t* a, uint32_t b0, uint32_t b1) {
    asm volatile(
        "mma.sync.aligned.m16n8k16.row.col.f32.f16.f16.f32 "
        "{%0,%1,%2,%3}, {%4,%5,%6,%7}, {%8,%9}, {%0,%1,%2,%3};"
        : "+f"(d[0]), "+f"(d[1]), "+f"(d[2]), "+f"(d[3])
        : "r"(a[0]), "r"(a[1]), "r"(a[2]), "r"(a[3]), "r"(b0), "r"(b1));
}
__device__ __forceinline__ uint32_t packh2(float a, float b) {
    __half2 h = __floats2half2_rn(a, b);
    return *(uint32_t*)&h;
}

// ---------------------------------------------------------------------------
// fp16 GEMM: C[M,N] = A[M,K] @ B[K,N], fp32 accum. B native [K][N] via
// ldmatrix.trans. CTA 128x128, BK=64, 3-stage cp.async, 8 warps (2x4).
// ---------------------------------------------------------------------------
#define GROWA 144
#define GROWB 272
#define GTILE_A (128 * GROWA)
#define GTILE_B (64 * GROWB)
#define GSTAGE (GTILE_A + GTILE_B)
#define GSMEM_TOTAL (3 * GSTAGE)

template <bool HALF_OUT>
__global__ __launch_bounds__(256, 1)
void gemm_fp16_kernel(const __half* __restrict__ A,
                      const __half* __restrict__ Bm,
                      void* __restrict__ Cc, int Ndim, int Kdim) {
    uint32_t sb = smem_to_u32(dynsmem);
    const int tid = threadIdx.x;
    const int wid = tid >> 5;
    const int lane = tid & 31;
    const int m0 = blockIdx.y * 128;
    const int n0 = blockIdx.x * 128;
    const int warp_m = (wid >> 2) * 64;
    const int warp_n = (wid & 3) * 32;

    const __half* Abase = A + (size_t)m0 * Kdim;
    const __half* Bbase = Bm + n0;

    auto fill = [&](int stage, int chunk) {
        const int k0 = chunk << 6;
        uint32_t so = sb + stage * GSTAGE;
#pragma unroll
        for (int it = 0; it < 4; it++) {
            int w = tid + it * 256;
            int row = w >> 3, ch = w & 7;
            uint32_t d = so + row * GROWA + ch * 16;
            const void* gA = Abase + (size_t)row * Kdim + k0 + ch * 8;
            asm volatile("cp.async.cg.shared.global [%0], [%1], 16;\n" :: "r"(d), "l"(gA));
        }
#pragma unroll
        for (int it = 0; it < 4; it++) {
            int w = tid + it * 256;
            int row = w >> 4, ch = w & 15;
            uint32_t d = so + GTILE_A + row * GROWB + ch * 16;
            const void* gB = Bbase + (size_t)(k0 + row) * Ndim + ch * 8;
            asm volatile("cp.async.cg.shared.global [%0], [%1], 16;\n" :: "r"(d), "l"(gB));
        }
    };

    float acc[4][4][4];
#pragma unroll
    for (int i = 0; i < 4; i++)
#pragma unroll
        for (int j = 0; j < 4; j++)
#pragma unroll
            for (int e = 0; e < 4; e++) acc[i][j][e] = 0.0f;

    const int NC = Kdim >> 6;

    fill(0, 0);
    asm volatile("cp.async.commit_group;\n" ::: "memory");
    fill(1, 1);
    asm volatile("cp.async.commit_group;\n" ::: "memory");

    const int a_row = lane & 15;
    const int a_ch = lane >> 4;
    const int b_row = (lane & 7) + ((lane & 8) ? 8 : 0);
    const int b_cb = (lane & 16) ? 16 : 0;

    for (int c = 0; c < NC; c++) {
        if (c + 2 < NC) fill((c + 2) % 3, c + 2);
        asm volatile("cp.async.commit_group;\n" ::: "memory");
        asm volatile("cp.async.wait_group 2;\n" ::: "memory");
        __syncthreads();

        uint32_t sA = sb + (c % 3) * GSTAGE;
        uint32_t sB = sA + GTILE_A;

#pragma unroll
        for (int ks = 0; ks < 4; ks++) {
            uint32_t ah[4][4];
#pragma unroll
            for (int mi = 0; mi < 4; mi++)
                ldsm_x4(ah[mi], sA + (warp_m + mi * 16 + a_row) * GROWA + ks * 32 + a_ch * 16);
            uint32_t bf[4][2];
#pragma unroll
            for (int j = 0; j < 2; j++) {
                uint32_t t4[4];
                ldsm_x4_t(t4, sB + (ks * 16 + b_row) * GROWB + warp_n * 2 + j * 32 + b_cb);
                bf[j * 2][0] = t4[0]; bf[j * 2][1] = t4[1];
                bf[j * 2 + 1][0] = t4[2]; bf[j * 2 + 1][1] = t4[3];
            }
#pragma unroll
            for (int mi = 0; mi < 4; mi++)
#pragma unroll
                for (int ni = 0; ni < 4; ni++)
                    mma16816h(acc[mi][ni], ah[mi], bf[ni][0], bf[ni][1]);
        }
        __syncthreads();
    }

#pragma unroll
    for (int mi = 0; mi < 4; mi++) {
#pragma unroll
        for (int ni = 0; ni < 4; ni++) {
            int r = m0 + warp_m + mi * 16 + (lane >> 2);
            int cc = n0 + warp_n + ni * 8 + 2 * (lane & 3);
            if (HALF_OUT) {
                __half* C = (__half*)Cc;
                *(__half2*)(C + (size_t)r * Ndim + cc) =
                    __floats2half2_rn(acc[mi][ni][0], acc[mi][ni][1]);
                *(__half2*)(C + (size_t)(r + 8) * Ndim + cc) =
                    __floats2half2_rn(acc[mi][ni][2], acc[mi][ni][3]);
            } else {
                float* C = (float*)Cc;
                *(float2*)(C + (size_t)r * Ndim + cc) = make_float2(acc[mi][ni][0], acc[mi][ni][1]);
                *(float2*)(C + (size_t)(r + 8) * Ndim + cc) = make_float2(acc[mi][ni][2], acc[mi][ni][3]);
            }
        }
    }
}

// ---------------------------------------------------------------------------
// HMMA fp16 flash attention, double-buffered K/V, HEAVY-FIRST q-tile order.
// ---------------------------------------------------------------------------
#define AROW 136
#define ATILE (64 * AROW)
#define ATILEB (ATILE * 2)
#define ASMEM_TOTAL (5 * ATILEB)

__global__ __launch_bounds__(128, 2)
void attn_hmma_kernel(const int* __restrict__ seq_lengths) {
    const uint32_t sbase = smem_to_u32(dynsmem);
    const uint32_t qsb = sbase;

    const int b = blockIdx.z;
    const int h = blockIdx.y;
    const int q0 = (gridDim.x - 1 - blockIdx.x) * 64;   // heavy tiles scheduled first
    const int hk = h >> 2;
    const int tid = threadIdx.x;
    const int warp = tid >> 5;
    const int lane = tid & 31;
    const int seqlen = seq_lengths[b];
    const int bT = b * T_;
    const int wq0 = q0 + warp * 16;
    const int r0 = lane >> 2;

    const int kthi = q0 >> 6;
    const int ktlo = (q0 > WINDOW_) ? ((q0 - WINDOW_) >> 6) : 0;
    const int extra = (ktlo > 0) ? 1 : 0;
    const int nt = (kthi - ktlo + 1) + extra;

    auto kt_of = [&](int it) { return extra ? ((it == 0) ? 0 : (ktlo + it - 1)) : it; };

    auto kv_load = [&](int it, int buf) {
        const int kbase = kt_of(it) * 64;
        const uint32_t kb = sbase + (1 + 2 * buf) * ATILEB;
        const uint32_t vb = sbase + (2 + 2 * buf) * ATILEB;
#pragma unroll
        for (int i = 0; i < 8; i++) {
            int id = tid + i * 128;
            int row = id >> 4, c = id & 15;
            size_t rbase = (size_t)(bT + kbase + row) * QKVC_ + hk * 128 + c * 8;
            uint32_t soff = row * 272 + c * 16;
            const void* gk = g_qkv + rbase + C_;
            const void* gv = g_qkv + rbase + C_ + KVC_;
            asm volatile("cp.async.cg.shared.global [%0], [%1], 16;\n" :: "r"(kb + soff), "l"(gk));
            asm volatile("cp.async.cg.shared.global [%0], [%1], 16;\n" :: "r"(vb + soff), "l"(gv));
        }
    };

#pragma unroll
    for (int i = 0; i < 8; i++) {
        int id = tid + i * 128;
        int row = id >> 4, c = id & 15;
        const void* g = g_qkv + (size_t)(bT + q0 + row) * QKVC_ + h * 128 + c * 8;
        uint32_t d = qsb + row * 272 + c * 16;
        asm volatile("cp.async.cg.shared.global [%0], [%1], 16;\n" :: "r"(d), "l"(g));
    }
    asm volatile("cp.async.commit_group;\n" ::: "memory");
    kv_load(0, 0);
    asm volatile("cp.async.commit_group;\n" ::: "memory");
    asm volatile("cp.async.wait_group 1;\n" ::: "memory");
    __syncthreads();

    uint32_t qf[8][4];
    {
        const int lrow = (lane & 7) + ((lane & 8) ? 8 : 0);
        const int lcol = (lane & 16) ? 16 : 0;
#pragma unroll
        for (int ks = 0; ks < 8; ks++)
            ldsm_x4(qf[ks], qsb + (warp * 16 + lrow) * 272 + ks * 32 + lcol);
    }

    float O[16][4];
#pragma unroll
    for (int t = 0; t < 16; t++)
#pragma unroll
        for (int e = 0; e < 4; e++) O[t][e] = 0.0f;
    float m0r = -1e30f, m1r = -1e30f, l0r = 0.0f, l1r = 0.0f;

    const int krowA = (lane & 7) + ((lane & 16) ? 8 : 0);
    const int kcolB = (lane & 8) ? 16 : 0;
    const int vrowA = (lane & 7) + ((lane & 8) ? 8 : 0);
    const int vcolB = (lane & 16) ? 16 : 0;

    for (int it = 0; it < nt; it++) {
        const int buf = it & 1;
        const int kbase = kt_of(it) * 64;

        if (it + 1 < nt) {
            kv_load(it + 1, buf ^ 1);
            asm volatile("cp.async.commit_group;\n" ::: "memory");
            asm volatile("cp.async.wait_group 1;\n" ::: "memory");
        } else {
            asm volatile("cp.async.wait_group 0;\n" ::: "memory");
        }
        __syncthreads();

        const uint32_t ksb = sbase + (1 + 2 * buf) * ATILEB;
        const uint32_t vsb = sbase + (2 + 2 * buf) * ATILEB;

        float S[8][4];
#pragma unroll
        for (int j = 0; j < 8; j++)
#pragma unroll
            for (int e = 0; e < 4; e++) S[j][e] = 0.0f;
#pragma unroll
        for (int ks = 0; ks < 8; ks++) {
#pragma unroll
            for (int np = 0; np < 4; np++) {
                uint32_t kf[4];
                ldsm_x4(kf, ksb + (np * 16 + krowA) * 272 + ks * 32 + kcolB);
                mma16816h(S[2 * np], qf[ks], kf[0], kf[1]);
                mma16816h(S[2 * np + 1], qf[ks], kf[2], kf[3]);
            }
        }

        const bool needmask = !((kbase + 63 <= wq0) && (wq0 + 15 - kbase <= WINDOW_));
        if (needmask) {
#pragma unroll
            for (int j = 0; j < 8; j++) {
                int kk = kbase + j * 8 + 2 * (lane & 3);
#pragma unroll
                for (int e = 0; e < 4; e++) {
                    int q = wq0 + r0 + ((e >= 2) ? 8 : 0);
                    int k = kk + (e & 1);
                    bool ok = (k <= q) && (((q - k) <= WINDOW_) || (k < SINK_));
                    if (!ok) S[j][e] = -1e30f;
                }
            }
        }

        float mx0 = -1e30f, mx1 = -1e30f;
#pragma unroll
        for (int j = 0; j < 8; j++) {
            mx0 = fmaxf(mx0, fmaxf(S[j][0], S[j][1]));
            mx1 = fmaxf(mx1, fmaxf(S[j][2], S[j][3]));
        }
        mx0 = fmaxf(mx0, __shfl_xor_sync(0xffffffffu, mx0, 1));
        mx0 = fmaxf(mx0, __shfl_xor_sync(0xffffffffu, mx0, 2));
        mx1 = fmaxf(mx1, __shfl_xor_sync(0xffffffffu, mx1, 1));
        mx1 = fmaxf(mx1, __shfl_xor_sync(0xffffffffu, mx1, 2));

        float mn0 = fmaxf(m0r, mx0);
        float mn1 = fmaxf(m1r, mx1);
        float a0 = __expf(m0r - mn0);
        float a1 = __expf(m1r - mn1);
        float s0 = 0.0f, s1 = 0.0f;
#pragma unroll
        for (int j = 0; j < 8; j++) {
            S[j][0] = __expf(S[j][0] - mn0);
            S[j][1] = __expf(S[j][1] - mn0);
            S[j][2] = __expf(S[j][2] - mn1);
            S[j][3] = __expf(S[j][3] - mn1);
            s0 += S[j][0] + S[j][1];
            s1 += S[j][2] + S[j][3];
        }
        s0 += __shfl_xor_sync(0xffffffffu, s0, 1);
        s0 += __shfl_xor_sync(0xffffffffu, s0, 2);
        s1 += __shfl_xor_sync(0xffffffffu, s1, 1);
        s1 += __shfl_xor_sync(0xffffffffu, s1, 2);

        l0r = l0r * a0 + s0;
        l1r = l1r * a1 + s1;
        m0r = mn0;
        m1r = mn1;
#pragma unroll
        for (int t = 0; t < 16; t++) {
            O[t][0] *= a0; O[t][1] *= a0;
            O[t][2] *= a1; O[t][3] *= a1;
        }

#pragma unroll
        for (int ks = 0; ks < 4; ks++) {
            uint32_t pa[4];
            pa[0] = packh2(S[2 * ks][0], S[2 * ks][1]);
            pa[1] = packh2(S[2 * ks][2], S[2 * ks][3]);
            pa[2] = packh2(S[2 * ks + 1][0], S[2 * ks + 1][1]);
            pa[3] = packh2(S[2 * ks + 1][2], S[2 * ks + 1][3]);
#pragma unroll
            for (int nq = 0; nq < 8; nq++) {
                uint32_t vf[4];
                ldsm_x4_t(vf, vsb + (ks * 16 + vrowA) * 272 + nq * 32 + vcolB);
                mma16816h(O[2 * nq], pa, vf[0], vf[1]);
                mma16816h(O[2 * nq + 1], pa, vf[2], vf[3]);
            }
        }
        __syncthreads();
    }

    const int qr0 = wq0 + r0;
    const int qr1 = qr0 + 8;
    float inv0 = (qr0 < seqlen) ? (1.0f / l0r) : 0.0f;
    float inv1 = (qr1 < seqlen) ? (1.0f / l1r) : 0.0f;
#pragma unroll
    for (int t = 0; t < 16; t++) {
        int col = h * 128 + t * 8 + 2 * (lane & 3);
        *(__half2*)(g_yh + (size_t)(bT + qr0) * C_ + col) =
            __floats2half2_rn(O[t][0] * inv0, O[t][1] * inv0);
        *(__half2*)(g_yh + (size_t)(bT + qr1) * C_ + col) =
            __floats2half2_rn(O[t][2] * inv1, O[t][3] * inv1);
    }
}

// ---------------------------------------------------------------------------
// Launch
// ---------------------------------------------------------------------------
extern "C" void kernel_launch(void* const* d_in, const int* in_sizes, int n_in,
                              void* d_out, int out_size) {
    const float* x  = (const float*)d_in[0];
    const float* Wq = (const float*)d_in[1];
    const float* Wk = (const float*)d_in[2];
    const float* Wv = (const float*)d_in[3];
    const float* Wo = (const float*)d_in[4];
    const int* seq_lengths = (const int*)d_in[5];
    float* out = (float*)d_out;

    __half *xh, *qkv, *yh, *wqkv, *wo;
    cudaGetSymbolAddress((void**)&xh, g_xh);
    cudaGetSymbolAddress((void**)&qkv, g_qkv);
    cudaGetSymbolAddress((void**)&yh, g_yh);
    cudaGetSymbolAddress((void**)&wqkv, g_wqkv);
    cudaGetSymbolAddress((void**)&wo, g_wo);

    const int M = B_ * T_;  // 4096

    cudaFuncSetAttribute((const void*)gemm_fp16_kernel<true>,
                         cudaFuncAttributeMaxDynamicSharedMemorySize, GSMEM_TOTAL);
    cudaFuncSetAttribute((const void*)gemm_fp16_kernel<false>,
                         cudaFuncAttributeMaxDynamicSharedMemorySize, GSMEM_TOTAL);
    cudaFuncSetAttribute((const void*)attn_hmma_kernel,
                         cudaFuncAttributeMaxDynamicSharedMemorySize, ASMEM_TOTAL);

    // Prep: x conversion + single fused weight conversion + rope table
    {
        int n = M * C_;
        conv_half_kernel<<<n / 4 / 256, 256>>>(x, xh, n);
        int wtot = (2 * C_ * C_ + 2 * C_ * KVC_) / 4;   // float4 units
        conv_weights_kernel<<<(wtot + 255) / 256, 256>>>(Wq, Wk, Wv, Wo, wqkv, wo);
        rope_table_kernel<<<(T_ * 64) / 256, 256>>>();
    }

    // Fused QKV projection (B native [K][N])
    gemm_fp16_kernel<true><<<dim3(QKVC_ / 128, M / 128), 256, GSMEM_TOTAL>>>(
        xh, wqkv, qkv, QKVC_, C_);

    // RoPE apply
    {
        int total = M * (H_ + HKV_) * 64;
        rope_apply_kernel<<<(total + 255) / 256, 256>>>(qkv, total);
    }

    // Attention (heavy-first ordering)
    attn_hmma_kernel<<<dim3(T_ / 64, H_, B_), 128, ASMEM_TOTAL>>>(seq_lengths);

    // Output projection (fp32 out)
    gemm_fp16_kernel<false><<<dim3(C_ / 128, M / 128), 256, GSMEM_TOTAL>>>(
        yh, wo, out, C_, C_);
}